// round 1
// baseline (speedup 1.0000x reference)
#include <cuda_runtime.h>
#include <math.h>

#define NN 50000
#define MM 12
#define AA 64
#define NBRD 41
#define TWOA 128
#define BB 1000
#define NPCC 50
#define ORIG 92
#define RTOT (NN*MM)          // 600000 edge rows
#define EPSB 1e-5f

// ---------------- device scratch (no allocations allowed) ----------------
__device__ float  g_x[NN*AA];                 // 12.8 MB  current atom features
__device__ float  g_summed[NN*AA];            // 12.8 MB
__device__ float  g_P1[NN*TWOA];              // 25.6 MB  x @ W_self + b
__device__ float  g_P2[NN*TWOA];              // 25.6 MB  x @ W_nbr
__device__ float  g_gated[RTOT*TWOA];         // 307 MB   pre-BN gated
__device__ double g_sum[TWOA];
__device__ double g_sumsq[TWOA];
__device__ float  g_scale1[TWOA], g_shift1[TWOA];   // bn1 fused scale/shift
__device__ float  g_scale2[AA],   g_shift2[AA];     // bn2 fused scale/shift
__device__ float  g_logp[BB*NPCC*6];

// ---------------- math helpers ----------------
__device__ __forceinline__ float softplusf(float x) {
    // stable: max(x,0) + log1p(exp(-|x|))
    return fmaxf(x, 0.0f) + log1pf(expf(-fabsf(x)));
}
__device__ __forceinline__ float sigmoidf(float x) {
    return 1.0f / (1.0f + expf(-x));
}

// ---------------- kernels ----------------
__global__ void k_zero_stats() {
    int t = threadIdx.x;
    if (t < TWOA) { g_sum[t] = 0.0; g_sumsq[t] = 0.0; }
}

// x = atom_fea @ emb_w   (50000x92)@(92x64)
__global__ void k_embed(const float* __restrict__ afea, const float* __restrict__ embw) {
    __shared__ float ws[ORIG*AA];      // 23.5 KB
    __shared__ float xs[4*ORIG];
    int tid = threadIdx.x;             // blockDim = 64
    for (int i = tid; i < ORIG*AA; i += 64) ws[i] = embw[i];
    __syncthreads();
    for (int g = blockIdx.x; g < NN/4; g += gridDim.x) {
        int n0 = g * 4;
        for (int i = tid; i < 4*ORIG; i += 64) xs[i] = afea[n0*ORIG + i];
        __syncthreads();
        float a0 = 0.f, a1 = 0.f, a2 = 0.f, a3 = 0.f;
        #pragma unroll 4
        for (int k = 0; k < ORIG; k++) {
            float w = ws[k*AA + tid];
            a0 += xs[k]*w; a1 += xs[ORIG+k]*w; a2 += xs[2*ORIG+k]*w; a3 += xs[3*ORIG+k]*w;
        }
        g_x[(n0+0)*AA + tid] = a0;
        g_x[(n0+1)*AA + tid] = a1;
        g_x[(n0+2)*AA + tid] = a2;
        g_x[(n0+3)*AA + tid] = a3;
        __syncthreads();
    }
}

// P1[n] = x[n] @ W[0:64] + b ; P2[n] = x[n] @ W[64:128]
// dynamic shared: 128*128 floats (64KB) for W rows 0..127
__global__ void k_proj(const float* __restrict__ w, const float* __restrict__ bias) {
    extern __shared__ float ws[];          // 128*TWOA floats
    __shared__ float xs[4*AA];
    int tid = threadIdx.x;                 // blockDim = 128
    for (int i = tid; i < 128*TWOA; i += 128) ws[i] = w[i];
    __syncthreads();
    float bc = bias[tid];
    for (int g = blockIdx.x; g < NN/4; g += gridDim.x) {
        int n0 = g * 4;
        for (int i = tid; i < 4*AA; i += 128) xs[i] = g_x[n0*AA + i];
        __syncthreads();
        float p1[4] = {bc, bc, bc, bc};
        float p2[4] = {0.f, 0.f, 0.f, 0.f};
        #pragma unroll 8
        for (int a = 0; a < AA; a++) {
            float w1 = ws[a*TWOA + tid];
            float w2 = ws[(AA+a)*TWOA + tid];
            #pragma unroll
            for (int r = 0; r < 4; r++) {
                float xv = xs[r*AA + a];
                p1[r] += xv * w1;
                p2[r] += xv * w2;
            }
        }
        #pragma unroll
        for (int r = 0; r < 4; r++) {
            g_P1[(n0+r)*TWOA + tid] = p1[r];
            g_P2[(n0+r)*TWOA + tid] = p2[r];
        }
        __syncthreads();
    }
}

// gated[row] = P1[n] + P2[nbr] + nbr_fea[row] @ W_edge ; accumulate bn1 stats
// blockDim = 256 (8 warps); each warp processes chunks of 8 edge rows.
__global__ void k_edge(const float* __restrict__ we,       // 41x128
                       const float* __restrict__ nbrf,     // (N,M,41)
                       const int*   __restrict__ nidx) {   // (N,M)
    __shared__ float4 ws4[NBRD*32];        // 21 KB  (41 x 128 floats)
    __shared__ float  nfs[8][8][NBRD];     // 10.5 KB per-warp row buffers
    __shared__ float  redS[TWOA], redQ[TWOA];
    int tid = threadIdx.x;
    {
        float* wf = (float*)ws4;
        for (int i = tid; i < NBRD*TWOA; i += 256) wf[i] = we[i];
    }
    __syncthreads();

    int w    = tid >> 5;
    int lane = tid & 31;
    int wg   = blockIdx.x * 8 + w;
    int nw   = gridDim.x * 8;

    float s0=0,s1=0,s2=0,s3=0, q0=0,q1=0,q2=0,q3=0;

    for (int ch = wg; ch < RTOT/8; ch += nw) {
        int r0 = ch * 8;
        #pragma unroll
        for (int rr = 0; rr < 8; rr++) {
            int row = r0 + rr;
            for (int k = lane; k < NBRD; k += 32) nfs[w][rr][k] = nbrf[row*NBRD + k];
        }
        __syncwarp();
        float4 acc[8];
        #pragma unroll
        for (int rr = 0; rr < 8; rr++) {
            int row = r0 + rr;
            int n = row / MM;
            int j = nidx[row];
            float4 a  = *(const float4*)&g_P1[n*TWOA + lane*4];
            float4 b4 = *(const float4*)&g_P2[j*TWOA + lane*4];
            acc[rr].x = a.x + b4.x; acc[rr].y = a.y + b4.y;
            acc[rr].z = a.z + b4.z; acc[rr].w = a.w + b4.w;
        }
        #pragma unroll
        for (int k = 0; k < NBRD; k++) {
            float4 wv = ws4[k*32 + lane];
            #pragma unroll
            for (int rr = 0; rr < 8; rr++) {
                float f = nfs[w][rr][k];
                acc[rr].x += f*wv.x; acc[rr].y += f*wv.y;
                acc[rr].z += f*wv.z; acc[rr].w += f*wv.w;
            }
        }
        #pragma unroll
        for (int rr = 0; rr < 8; rr++) {
            *(float4*)&g_gated[(r0+rr)*TWOA + lane*4] = acc[rr];
            s0 += acc[rr].x; q0 += acc[rr].x*acc[rr].x;
            s1 += acc[rr].y; q1 += acc[rr].y*acc[rr].y;
            s2 += acc[rr].z; q2 += acc[rr].z*acc[rr].z;
            s3 += acc[rr].w; q3 += acc[rr].w*acc[rr].w;
        }
        __syncwarp();
    }

    if (tid < TWOA) { redS[tid] = 0.f; redQ[tid] = 0.f; }
    __syncthreads();
    int c = lane * 4;
    atomicAdd(&redS[c+0], s0); atomicAdd(&redQ[c+0], q0);
    atomicAdd(&redS[c+1], s1); atomicAdd(&redQ[c+1], q1);
    atomicAdd(&redS[c+2], s2); atomicAdd(&redQ[c+2], q2);
    atomicAdd(&redS[c+3], s3); atomicAdd(&redQ[c+3], q3);
    __syncthreads();
    if (tid < TWOA) {
        atomicAdd(&g_sum[tid],   (double)redS[tid]);
        atomicAdd(&g_sumsq[tid], (double)redQ[tid]);
    }
}

// finalize bn stats -> fused scale/shift; zero accumulators for next use
__global__ void k_bnstat(int ncols, double invR, int which,
                         const float* __restrict__ g, const float* __restrict__ b) {
    int t = threadIdx.x;
    if (t < ncols) {
        double s = g_sum[t], q = g_sumsq[t];
        double mean = s * invR;
        double var  = q * invR - mean * mean;
        float istd = rsqrtf((float)var + EPSB);
        float sc = istd * g[t];
        float sh = b[t] - (float)mean * sc;
        if (which == 1) { g_scale1[t] = sc; g_shift1[t] = sh; }
        else            { g_scale2[t] = sc; g_shift2[t] = sh; }
        g_sum[t] = 0.0; g_sumsq[t] = 0.0;
    }
}

// apply bn1, sigmoid(filter)*softplus(core), sum over M -> summed; accumulate bn2 stats
__global__ void k_apply() {
    int a = threadIdx.x;   // 0..63, blockDim (64,4)
    float scF = g_scale1[a],    shF = g_shift1[a];
    float scC = g_scale1[a+64], shC = g_shift1[a+64];
    float ls = 0.f, lq = 0.f;
    for (int n = blockIdx.x*4 + threadIdx.y; n < NN; n += gridDim.x*4) {
        const float* gp = &g_gated[n*(MM*TWOA)];
        float s = 0.f;
        #pragma unroll
        for (int m = 0; m < MM; m++) {
            float f = gp[m*TWOA + a]     * scF + shF;
            float c = gp[m*TWOA + 64 + a]* scC + shC;
            s += sigmoidf(f) * softplusf(c);
        }
        g_summed[n*AA + a] = s;
        ls += s; lq += s*s;
    }
    __shared__ float rS[AA], rQ[AA];
    if (threadIdx.y == 0) { rS[a] = 0.f; rQ[a] = 0.f; }
    __syncthreads();
    atomicAdd(&rS[a], ls); atomicAdd(&rQ[a], lq);
    __syncthreads();
    if (threadIdx.y == 0) {
        atomicAdd(&g_sum[a],   (double)rS[a]);
        atomicAdd(&g_sumsq[a], (double)rQ[a]);
    }
}

// x = softplus(x + bn2(summed))
__global__ void k_update() {
    int idx = blockIdx.x * blockDim.x + threadIdx.x;
    if (idx >= NN*AA) return;
    int a = idx & (AA-1);
    float v = g_x[idx] + g_summed[idx] * g_scale2[a] + g_shift2[a];
    g_x[idx] = softplusf(v);
}

// per-atom: quadratic forms -> fc1 -> log_softmax -> g_logp ; atom_feature -> out2
// dynamic shared: Wt(6*64*64, transposed [o][e][d]) + afw(64*92) + v(64) + q(8)
__global__ void k_final(const int* __restrict__ cidx,
                        const float* __restrict__ adjw, const float* __restrict__ adjb,
                        const float* __restrict__ fc1w, const float* __restrict__ fc1b,
                        const float* __restrict__ afw,  const float* __restrict__ afb,
                        float* __restrict__ out2) {
    extern __shared__ float smem[];
    float* Wt   = smem;            // 24576
    float* afws = Wt + 6*64*64;    // 5888
    float* vsh  = afws + AA*ORIG;  // 64
    float* qsh  = vsh + 64;        // 8
    int tid = threadIdx.x;         // 256
    for (int i = tid; i < 6*64*64; i += 256) {
        int o = i >> 12, rem = i & 4095, d = rem >> 6, e = rem & 63;
        Wt[o*4096 + e*64 + d] = adjw[i];
    }
    for (int i = tid; i < AA*ORIG; i += 256) afws[i] = afw[i];
    __syncthreads();

    int w = tid >> 5, lane = tid & 31;
    for (int t = blockIdx.x; t < BB*NPCC; t += gridDim.x) {
        int idx = cidx[t];
        if (tid < 64) vsh[tid] = g_x[idx*AA + tid];
        __syncthreads();
        if (w < 6) {
            const float* Wo = Wt + w*4096;
            float s1 = 0.f, s2 = 0.f;
            #pragma unroll 8
            for (int e = 0; e < 64; e++) {
                float ve = vsh[e];
                s1 += Wo[e*64 + lane]      * ve;
                s2 += Wo[e*64 + lane + 32] * ve;
            }
            float part = vsh[lane]*s1 + vsh[lane+32]*s2;
            #pragma unroll
            for (int off = 16; off; off >>= 1)
                part += __shfl_down_sync(0xffffffffu, part, off);
            if (lane == 0) qsh[w] = part + adjb[w];
        } else {
            int u = tid - 192;                       // 0..63
            int u2 = (u < ORIG-64) ? (u + 64) : 0;
            float acc0 = afb[u];
            float acc1 = afb[u2];
            #pragma unroll 8
            for (int a = 0; a < AA; a++) {
                float va = vsh[a];
                acc0 += va * afws[a*ORIG + u];
                acc1 += va * afws[a*ORIG + u2];
            }
            out2[t*ORIG + u] = acc0;
            if (u < ORIG-64) out2[t*ORIG + u2] = acc1;
        }
        __syncthreads();
        if (tid == 0) {
            float q2[6];
            #pragma unroll
            for (int j = 0; j < 6; j++) {
                float a = fc1b[j];
                #pragma unroll
                for (int o = 0; o < 6; o++) a += qsh[o] * fc1w[o*6 + j];
                q2[j] = a;
            }
            float mx = q2[0];
            #pragma unroll
            for (int j = 1; j < 6; j++) mx = fmaxf(mx, q2[j]);
            float se = 0.f;
            #pragma unroll
            for (int j = 0; j < 6; j++) se += expf(q2[j] - mx);
            float lse = logf(se);
            #pragma unroll
            for (int j = 0; j < 6; j++) g_logp[t*6 + j] = q2[j] - mx - lse;
        }
    }
}

// edge_prob broadcast: out[b, i*50+n, o] = logp[b, n, o]
__global__ void k_edgeprob(float* __restrict__ out) {
    __shared__ float sh[NPCC*6];
    int b = blockIdx.x;
    for (int i = threadIdx.x; i < NPCC*6; i += 256) sh[i] = g_logp[b*NPCC*6 + i];
    __syncthreads();
    float* o = out + (size_t)b * (NPCC*NPCC*6);
    for (int t = threadIdx.x; t < NPCC*NPCC*6; t += 256) o[t] = sh[t % (NPCC*6)];
}

// ---------------- host ----------------
extern "C" void kernel_launch(void* const* d_in, const int* in_sizes, int n_in,
                              void* d_out, int out_size) {
    const float* atom_fea = (const float*)d_in[0];
    const float* nbr_fea  = (const float*)d_in[1];
    const int*   nbr_idx  = (const int*)  d_in[2];
    const int*   cidx     = (const int*)  d_in[3];
    const float* emb_w    = (const float*)d_in[4];
    const float* fcw      = (const float*)d_in[5];
    const float* fcb      = (const float*)d_in[6];
    const float* bn1g     = (const float*)d_in[7];
    const float* bn1b     = (const float*)d_in[8];
    const float* bn2g     = (const float*)d_in[9];
    const float* bn2b     = (const float*)d_in[10];
    const float* adjw     = (const float*)d_in[11];
    const float* adjb     = (const float*)d_in[12];
    const float* fc1w     = (const float*)d_in[13];
    const float* fc1b     = (const float*)d_in[14];
    const float* afw      = (const float*)d_in[15];
    const float* afb      = (const float*)d_in[16];
    float* out = (float*)d_out;

    const int PROJ_SMEM  = 128 * TWOA * sizeof(float);                      // 64 KB
    const int FINAL_SMEM = (6*64*64 + AA*ORIG + 64 + 8) * sizeof(float);    // ~122 KB
    cudaFuncSetAttribute(k_proj,  cudaFuncAttributeMaxDynamicSharedMemorySize, PROJ_SMEM);
    cudaFuncSetAttribute(k_final, cudaFuncAttributeMaxDynamicSharedMemorySize, FINAL_SMEM);

    k_zero_stats<<<1, 256>>>();
    k_embed<<<1184, 64>>>(atom_fea, emb_w);

    for (int i = 0; i < 3; i++) {
        const float* w = fcw + i * (2*AA + NBRD) * TWOA;   // (169,128) for layer i
        k_proj<<<592, 128, PROJ_SMEM>>>(w, fcb + i*TWOA);
        k_edge<<<1184, 256>>>(w + 2*AA*TWOA, nbr_fea, nbr_idx);
        k_bnstat<<<1, 128>>>(TWOA, 1.0 / (double)RTOT, 1, bn1g + i*TWOA, bn1b + i*TWOA);
        k_apply<<<592, dim3(64, 4)>>>();
        k_bnstat<<<1, 128>>>(AA, 1.0 / (double)NN, 2, bn2g + i*AA, bn2b + i*AA);
        k_update<<<(NN*AA + 255)/256, 256>>>();
    }

    float* out_atomfea = out + (size_t)BB * NPCC * NPCC * 6;   // +15,000,000
    k_final<<<592, 256, FINAL_SMEM>>>(cidx, adjw, adjb, fc1w, fc1b, afw, afb, out_atomfea);
    k_edgeprob<<<BB, 256>>>(out);
}

// round 2
// speedup vs baseline: 1.2117x; 1.2117x over previous
#include <cuda_runtime.h>
#include <math.h>

#define NN 50000
#define MM 12
#define AA 64
#define NBRD 41
#define TWOA 128
#define BB 1000
#define NPCC 50
#define ORIG 92
#define RTOT (NN*MM)          // 600000 edge rows
#define EPSB 1e-5f

typedef unsigned long long ull;

// ---------------- device scratch (no allocations allowed) ----------------
__device__ float  g_x[NN*AA];                 // 12.8 MB
__device__ float  g_summed[NN*AA];            // 12.8 MB
__device__ float  g_P1[NN*TWOA];              // 25.6 MB  x @ W_self + b
__device__ float  g_P2[NN*TWOA];              // 25.6 MB  x @ W_nbr
__device__ float  g_gated[RTOT*TWOA];         // 307 MB   pre-BN gated
__device__ double g_sum[TWOA];
__device__ double g_sumsq[TWOA];
__device__ float  g_scale1[TWOA], g_shift1[TWOA];
__device__ float  g_scale2[AA],   g_shift2[AA];
__device__ float  g_logp[BB*NPCC*6];

// ---------------- f32x2 packed-math helpers (SASS FFMA2 path) ----------------
__device__ __forceinline__ ull f2x_pack(float lo, float hi) {
    ull r; asm("mov.b64 %0, {%1, %2};" : "=l"(r) : "f"(lo), "f"(hi)); return r;
}
__device__ __forceinline__ void f2x_unpack(ull v, float& lo, float& hi) {
    asm("mov.b64 {%0, %1}, %2;" : "=f"(lo), "=f"(hi) : "l"(v));
}
__device__ __forceinline__ ull f2x_fma(ull a, ull b, ull c) {
    ull d; asm("fma.rn.f32x2 %0, %1, %2, %3;" : "=l"(d) : "l"(a), "l"(b), "l"(c)); return d;
}
__device__ __forceinline__ ull f2x_add(ull a, ull b) {
    ull d; asm("add.rn.f32x2 %0, %1, %2;" : "=l"(d) : "l"(a), "l"(b)); return d;
}

// ---------------- fast math helpers ----------------
__device__ __forceinline__ float softplus_fast(float x) {
    return fmaxf(x, 0.0f) + __logf(1.0f + __expf(-fabsf(x)));
}
__device__ __forceinline__ float sigmoid_fast(float x) {
    return __fdividef(1.0f, 1.0f + __expf(-x));
}

// ---------------- kernels ----------------
__global__ void k_zero_stats() {
    int t = threadIdx.x;
    if (t < TWOA) { g_sum[t] = 0.0; g_sumsq[t] = 0.0; }
}

// x = atom_fea @ emb_w   (50000x92)@(92x64)
__global__ void k_embed(const float* __restrict__ afea, const float* __restrict__ embw) {
    __shared__ float ws[ORIG*AA];
    __shared__ float xs[4*ORIG];
    int tid = threadIdx.x;             // blockDim = 64
    for (int i = tid; i < ORIG*AA; i += 64) ws[i] = embw[i];
    __syncthreads();
    for (int g = blockIdx.x; g < NN/4; g += gridDim.x) {
        int n0 = g * 4;
        for (int i = tid; i < 4*ORIG; i += 64) xs[i] = afea[n0*ORIG + i];
        __syncthreads();
        float a0 = 0.f, a1 = 0.f, a2 = 0.f, a3 = 0.f;
        #pragma unroll 4
        for (int k = 0; k < ORIG; k++) {
            float w = ws[k*AA + tid];
            a0 += xs[k]*w; a1 += xs[ORIG+k]*w; a2 += xs[2*ORIG+k]*w; a3 += xs[3*ORIG+k]*w;
        }
        g_x[(n0+0)*AA + tid] = a0;
        g_x[(n0+1)*AA + tid] = a1;
        g_x[(n0+2)*AA + tid] = a2;
        g_x[(n0+3)*AA + tid] = a3;
        __syncthreads();
    }
}

// P1[n] = x[n] @ W[0:64] + b ; P2[n] = x[n] @ W[64:128]  (f32x2 version)
// blockDim = 64; thread t owns columns 2t, 2t+1; 8 atoms per group.
__global__ void k_proj(const float* __restrict__ w, const float* __restrict__ bias) {
    extern __shared__ float ws[];          // 128*TWOA floats = 64 KB
    __shared__ float xs[8*AA];
    int t = threadIdx.x;                   // 64
    for (int i = t; i < 128*TWOA; i += 64) ws[i] = w[i];
    __syncthreads();
    ull bc = f2x_pack(bias[2*t], bias[2*t+1]);
    const ull* wv = (const ull*)ws;
    for (int g = blockIdx.x; g < NN/8; g += gridDim.x) {
        int n0 = g * 8;
        for (int i = t; i < 8*AA; i += 64) xs[i] = g_x[n0*AA + i];
        __syncthreads();
        ull p1[8], p2[8];
        #pragma unroll
        for (int r = 0; r < 8; r++) { p1[r] = bc; p2[r] = 0ull; }
        #pragma unroll 4
        for (int a = 0; a < AA; a++) {
            ull w1 = wv[a*64 + t];
            ull w2 = wv[(AA+a)*64 + t];
            #pragma unroll
            for (int r = 0; r < 8; r++) {
                float xf = xs[r*AA + a];
                ull xv = f2x_pack(xf, xf);
                p1[r] = f2x_fma(xv, w1, p1[r]);
                p2[r] = f2x_fma(xv, w2, p2[r]);
            }
        }
        #pragma unroll
        for (int r = 0; r < 8; r++) {
            ((ull*)&g_P1[(size_t)(n0+r)*TWOA])[t] = p1[r];
            ((ull*)&g_P2[(size_t)(n0+r)*TWOA])[t] = p2[r];
        }
        __syncthreads();
    }
}

// gated[row] = P1[n] + P2[nbr] + nbr_fea[row] @ W_edge ; accumulate bn1 stats.
// blockDim = 256 (8 warps); warp processes chunks of 8 edge rows; f32x2 math.
__global__ __launch_bounds__(256, 3)
void k_edge(const float* __restrict__ we,       // 41x128
            const float* __restrict__ nbrf,     // (N,M,41)
            const int*   __restrict__ nidx) {   // (N,M)
    __shared__ ulonglong2 wsv[NBRD*32];    // 21 KB  (41 x 128 floats)
    __shared__ float  nfs[8][8][NBRD];     // 10.5 KB per-warp row buffers
    __shared__ float  redS[TWOA], redQ[TWOA];
    int tid = threadIdx.x;
    {
        float* wf = (float*)wsv;
        for (int i = tid; i < NBRD*TWOA; i += 256) wf[i] = we[i];
    }
    __syncthreads();

    int w    = tid >> 5;
    int lane = tid & 31;
    int wg   = blockIdx.x * 8 + w;
    int nw   = gridDim.x * 8;

    ull s01 = 0ull, s23 = 0ull, q01 = 0ull, q23 = 0ull;

    for (int ch = wg; ch < RTOT/8; ch += nw) {
        int r0 = ch * 8;
        #pragma unroll
        for (int rr = 0; rr < 8; rr++) {
            int row = r0 + rr;
            for (int k = lane; k < NBRD; k += 32) nfs[w][rr][k] = nbrf[(size_t)row*NBRD + k];
        }
        __syncwarp();
        ull a01[8], a23[8];
        #pragma unroll
        for (int rr = 0; rr < 8; rr++) {
            int row = r0 + rr;
            int n = row / MM;
            int j = nidx[row];
            ulonglong2 pa = ((const ulonglong2*)&g_P1[(size_t)n*TWOA])[lane];
            ulonglong2 pb = ((const ulonglong2*)&g_P2[(size_t)j*TWOA])[lane];
            a01[rr] = f2x_add(pa.x, pb.x);
            a23[rr] = f2x_add(pa.y, pb.y);
        }
        #pragma unroll 1
        for (int k = 0; k < NBRD; k++) {
            ulonglong2 wv = wsv[k*32 + lane];
            #pragma unroll
            for (int rr = 0; rr < 8; rr++) {
                float f = nfs[w][rr][k];
                ull ff = f2x_pack(f, f);
                a01[rr] = f2x_fma(ff, wv.x, a01[rr]);
                a23[rr] = f2x_fma(ff, wv.y, a23[rr]);
            }
        }
        #pragma unroll
        for (int rr = 0; rr < 8; rr++) {
            ulonglong2 st; st.x = a01[rr]; st.y = a23[rr];
            *(ulonglong2*)&g_gated[(size_t)(r0+rr)*TWOA + lane*4] = st;
            s01 = f2x_add(s01, a01[rr]);
            s23 = f2x_add(s23, a23[rr]);
            q01 = f2x_fma(a01[rr], a01[rr], q01);
            q23 = f2x_fma(a23[rr], a23[rr], q23);
        }
        __syncwarp();
    }

    float s0,s1,s2,s3,q0,q1,q2,q3;
    f2x_unpack(s01, s0, s1); f2x_unpack(s23, s2, s3);
    f2x_unpack(q01, q0, q1); f2x_unpack(q23, q2, q3);

    if (tid < TWOA) { redS[tid] = 0.f; redQ[tid] = 0.f; }
    __syncthreads();
    int c = lane * 4;
    atomicAdd(&redS[c+0], s0); atomicAdd(&redQ[c+0], q0);
    atomicAdd(&redS[c+1], s1); atomicAdd(&redQ[c+1], q1);
    atomicAdd(&redS[c+2], s2); atomicAdd(&redQ[c+2], q2);
    atomicAdd(&redS[c+3], s3); atomicAdd(&redQ[c+3], q3);
    __syncthreads();
    if (tid < TWOA) {
        atomicAdd(&g_sum[tid],   (double)redS[tid]);
        atomicAdd(&g_sumsq[tid], (double)redQ[tid]);
    }
}

// finalize bn stats -> fused scale/shift; zero accumulators for next use
__global__ void k_bnstat(int ncols, double invR, int which,
                         const float* __restrict__ g, const float* __restrict__ b) {
    int t = threadIdx.x;
    if (t < ncols) {
        double s = g_sum[t], q = g_sumsq[t];
        double mean = s * invR;
        double var  = q * invR - mean * mean;
        float istd = rsqrtf((float)var + EPSB);
        float sc = istd * g[t];
        float sh = b[t] - (float)mean * sc;
        if (which == 1) { g_scale1[t] = sc; g_shift1[t] = sh; }
        else            { g_scale2[t] = sc; g_shift2[t] = sh; }
        g_sum[t] = 0.0; g_sumsq[t] = 0.0;
    }
}

// apply bn1, sigmoid(filter)*softplus(core), sum over M -> summed; accumulate bn2 stats
// blockDim (32,8): tx owns cols 2tx,2tx+1; 8 atoms per block-iteration.
__global__ void k_apply() {
    int tx = threadIdx.x, ty = threadIdx.y;
    int c0 = tx * 2;
    float2 scF = *(const float2*)&g_scale1[c0];
    float2 shF = *(const float2*)&g_shift1[c0];
    float2 scC = *(const float2*)&g_scale1[AA + c0];
    float2 shC = *(const float2*)&g_shift1[AA + c0];
    float ls0=0.f, lq0=0.f, ls1=0.f, lq1=0.f;
    for (int n = blockIdx.x*8 + ty; n < NN; n += gridDim.x*8) {
        const float* gp = &g_gated[(size_t)n*(MM*TWOA)];
        float sx = 0.f, sy = 0.f;
        #pragma unroll
        for (int m = 0; m < MM; m++) {
            float2 fv = *(const float2*)&gp[m*TWOA + c0];
            float2 cv = *(const float2*)&gp[m*TWOA + AA + c0];
            float f0 = fv.x*scF.x + shF.x, c0v = cv.x*scC.x + shC.x;
            float f1 = fv.y*scF.y + shF.y, c1v = cv.y*scC.y + shC.y;
            sx += sigmoid_fast(f0) * softplus_fast(c0v);
            sy += sigmoid_fast(f1) * softplus_fast(c1v);
        }
        float2 out; out.x = sx; out.y = sy;
        *(float2*)&g_summed[(size_t)n*AA + c0] = out;
        ls0 += sx; lq0 += sx*sx; ls1 += sy; lq1 += sy*sy;
    }
    __shared__ float rS[AA], rQ[AA];
    if (ty == 0) { rS[c0]=0.f; rS[c0+1]=0.f; rQ[c0]=0.f; rQ[c0+1]=0.f; }
    __syncthreads();
    atomicAdd(&rS[c0],   ls0); atomicAdd(&rQ[c0],   lq0);
    atomicAdd(&rS[c0+1], ls1); atomicAdd(&rQ[c0+1], lq1);
    __syncthreads();
    if (ty == 0) {
        atomicAdd(&g_sum[c0],     (double)rS[c0]);
        atomicAdd(&g_sumsq[c0],   (double)rQ[c0]);
        atomicAdd(&g_sum[c0+1],   (double)rS[c0+1]);
        atomicAdd(&g_sumsq[c0+1], (double)rQ[c0+1]);
    }
}

// x = softplus(x + bn2(summed))
__global__ void k_update() {
    int idx = blockIdx.x * blockDim.x + threadIdx.x;
    if (idx >= NN*AA) return;
    int a = idx & (AA-1);
    float v = g_x[idx] + g_summed[idx] * g_scale2[a] + g_shift2[a];
    g_x[idx] = softplus_fast(v);
}

// per-atom: quadratic forms -> fc1 -> log_softmax -> g_logp ; atom_feature -> out2
__global__ void k_final(const int* __restrict__ cidx,
                        const float* __restrict__ adjw, const float* __restrict__ adjb,
                        const float* __restrict__ fc1w, const float* __restrict__ fc1b,
                        const float* __restrict__ afw,  const float* __restrict__ afb,
                        float* __restrict__ out2) {
    extern __shared__ float smem[];
    float* Wt   = smem;            // 24576
    float* afws = Wt + 6*64*64;    // 5888
    float* vsh  = afws + AA*ORIG;  // 64
    float* qsh  = vsh + 64;        // 8
    int tid = threadIdx.x;         // 256
    for (int i = tid; i < 6*64*64; i += 256) {
        int o = i >> 12, rem = i & 4095, d = rem >> 6, e = rem & 63;
        Wt[o*4096 + e*64 + d] = adjw[i];
    }
    for (int i = tid; i < AA*ORIG; i += 256) afws[i] = afw[i];
    __syncthreads();

    int w = tid >> 5, lane = tid & 31;
    for (int t = blockIdx.x; t < BB*NPCC; t += gridDim.x) {
        int idx = cidx[t];
        if (tid < 64) vsh[tid] = g_x[idx*AA + tid];
        __syncthreads();
        if (w < 6) {
            const float* Wo = Wt + w*4096;
            float s1 = 0.f, s2 = 0.f;
            #pragma unroll 8
            for (int e = 0; e < 64; e++) {
                float ve = vsh[e];
                s1 += Wo[e*64 + lane]      * ve;
                s2 += Wo[e*64 + lane + 32] * ve;
            }
            float part = vsh[lane]*s1 + vsh[lane+32]*s2;
            #pragma unroll
            for (int off = 16; off; off >>= 1)
                part += __shfl_down_sync(0xffffffffu, part, off);
            if (lane == 0) qsh[w] = part + adjb[w];
        } else {
            int u = tid - 192;                       // 0..63
            int u2 = (u < ORIG-64) ? (u + 64) : 0;
            float acc0 = afb[u];
            float acc1 = afb[u2];
            #pragma unroll 8
            for (int a = 0; a < AA; a++) {
                float va = vsh[a];
                acc0 += va * afws[a*ORIG + u];
                acc1 += va * afws[a*ORIG + u2];
            }
            out2[(size_t)t*ORIG + u] = acc0;
            if (u < ORIG-64) out2[(size_t)t*ORIG + u2] = acc1;
        }
        __syncthreads();
        if (tid == 0) {
            float q2[6];
            #pragma unroll
            for (int j = 0; j < 6; j++) {
                float a = fc1b[j];
                #pragma unroll
                for (int o = 0; o < 6; o++) a += qsh[o] * fc1w[o*6 + j];
                q2[j] = a;
            }
            float mx = q2[0];
            #pragma unroll
            for (int j = 1; j < 6; j++) mx = fmaxf(mx, q2[j]);
            float se = 0.f;
            #pragma unroll
            for (int j = 0; j < 6; j++) se += __expf(q2[j] - mx);
            float lse = __logf(se);
            #pragma unroll
            for (int j = 0; j < 6; j++) g_logp[t*6 + j] = q2[j] - mx - lse;
        }
    }
}

// edge_prob broadcast: out[b, i*50+n, o] = logp[b, n, o]
__global__ void k_edgeprob(float* __restrict__ out) {
    __shared__ float sh[NPCC*6];
    int b = blockIdx.x;
    for (int i = threadIdx.x; i < NPCC*6; i += 256) sh[i] = g_logp[b*NPCC*6 + i];
    __syncthreads();
    float* o = out + (size_t)b * (NPCC*NPCC*6);
    for (int t = threadIdx.x; t < NPCC*NPCC*6; t += 256) o[t] = sh[t % (NPCC*6)];
}

// ---------------- host ----------------
extern "C" void kernel_launch(void* const* d_in, const int* in_sizes, int n_in,
                              void* d_out, int out_size) {
    const float* atom_fea = (const float*)d_in[0];
    const float* nbr_fea  = (const float*)d_in[1];
    const int*   nbr_idx  = (const int*)  d_in[2];
    const int*   cidx     = (const int*)  d_in[3];
    const float* emb_w    = (const float*)d_in[4];
    const float* fcw      = (const float*)d_in[5];
    const float* fcb      = (const float*)d_in[6];
    const float* bn1g     = (const float*)d_in[7];
    const float* bn1b     = (const float*)d_in[8];
    const float* bn2g     = (const float*)d_in[9];
    const float* bn2b     = (const float*)d_in[10];
    const float* adjw     = (const float*)d_in[11];
    const float* adjb     = (const float*)d_in[12];
    const float* fc1w     = (const float*)d_in[13];
    const float* fc1b     = (const float*)d_in[14];
    const float* afw      = (const float*)d_in[15];
    const float* afb      = (const float*)d_in[16];
    float* out = (float*)d_out;

    const int PROJ_SMEM  = 128 * TWOA * sizeof(float);                      // 64 KB
    const int FINAL_SMEM = (6*64*64 + AA*ORIG + 64 + 8) * sizeof(float);    // ~122 KB
    cudaFuncSetAttribute(k_proj,  cudaFuncAttributeMaxDynamicSharedMemorySize, PROJ_SMEM);
    cudaFuncSetAttribute(k_final, cudaFuncAttributeMaxDynamicSharedMemorySize, FINAL_SMEM);

    k_zero_stats<<<1, 256>>>();
    k_embed<<<1184, 64>>>(atom_fea, emb_w);

    for (int i = 0; i < 3; i++) {
        const float* w = fcw + i * (2*AA + NBRD) * TWOA;   // (169,128) for layer i
        k_proj<<<1184, 64, PROJ_SMEM>>>(w, fcb + i*TWOA);
        k_edge<<<1184, 256>>>(w + 2*AA*TWOA, nbr_fea, nbr_idx);
        k_bnstat<<<1, 128>>>(TWOA, 1.0 / (double)RTOT, 1, bn1g + i*TWOA, bn1b + i*TWOA);
        k_apply<<<1184, dim3(32, 8)>>>();
        k_bnstat<<<1, 128>>>(AA, 1.0 / (double)NN, 2, bn2g + i*AA, bn2b + i*AA);
        k_update<<<(NN*AA + 255)/256, 256>>>();
    }

    float* out_atomfea = out + (size_t)BB * NPCC * NPCC * 6;   // +15,000,000
    k_final<<<592, 256, FINAL_SMEM>>>(cidx, adjw, adjb, fc1w, fc1b, afw, afb, out_atomfea);
    k_edgeprob<<<BB, 256>>>(out);
}

// round 4
// speedup vs baseline: 2.1855x; 1.8037x over previous
#include <cuda_runtime.h>
#include <math.h>

#define NN 50000
#define MM 12
#define AA 64
#define NBRD 41
#define TWOA 128
#define BB 1000
#define NPCC 50
#define ORIG 92
#define RTOT (NN*MM)          // 600000 edge rows
#define EPSB 1e-5f

typedef unsigned long long ull;

// ---------------- device scratch ----------------
__device__ float  g_x[NN*AA];
__device__ float  g_summed[NN*AA];
__device__ float  g_P1[NN*TWOA];
__device__ float  g_P2[NN*TWOA];
__device__ float  g_gated[RTOT*TWOA];         // 307 MB
__device__ double g_sum[TWOA];
__device__ double g_sumsq[TWOA];
__device__ float  g_scale1[TWOA], g_shift1[TWOA];
__device__ float  g_scale2[AA],   g_shift2[AA];
__device__ float  g_logp[BB*NPCC*6];

// ---------------- f32x2 helpers ----------------
__device__ __forceinline__ ull f2x_pack(float lo, float hi) {
    ull r; asm("mov.b64 %0, {%1, %2};" : "=l"(r) : "f"(lo), "f"(hi)); return r;
}
__device__ __forceinline__ void f2x_unpack(ull v, float& lo, float& hi) {
    asm("mov.b64 {%0, %1}, %2;" : "=f"(lo), "=f"(hi) : "l"(v));
}
__device__ __forceinline__ ull f2x_fma(ull a, ull b, ull c) {
    ull d; asm("fma.rn.f32x2 %0, %1, %2, %3;" : "=l"(d) : "l"(a), "l"(b), "l"(c)); return d;
}
__device__ __forceinline__ ull f2x_add(ull a, ull b) {
    ull d; asm("add.rn.f32x2 %0, %1, %2;" : "=l"(d) : "l"(a), "l"(b)); return d;
}

// ---------------- fast math ----------------
__device__ __forceinline__ float softplus_fast(float x) {
    return fmaxf(x, 0.0f) + __logf(1.0f + __expf(-fabsf(x)));
}
__device__ __forceinline__ float sigmoid_fast(float x) {
    return __fdividef(1.0f, 1.0f + __expf(-x));
}

// ---------------- kernels ----------------
__global__ void k_zero_stats() {
    int t = threadIdx.x;
    if (t < TWOA) { g_sum[t] = 0.0; g_sumsq[t] = 0.0; }
}

// x = atom_fea @ emb_w   (50000x92)@(92x64)
__global__ void k_embed(const float* __restrict__ afea, const float* __restrict__ embw) {
    __shared__ float ws[ORIG*AA];
    __shared__ float xs[4*ORIG];
    int tid = threadIdx.x;             // 64
    for (int i = tid; i < ORIG*AA; i += 64) ws[i] = embw[i];
    __syncthreads();
    for (int g = blockIdx.x; g < NN/4; g += gridDim.x) {
        int n0 = g * 4;
        for (int i = tid; i < 4*ORIG; i += 64) xs[i] = afea[n0*ORIG + i];
        __syncthreads();
        float a0 = 0.f, a1 = 0.f, a2 = 0.f, a3 = 0.f;
        #pragma unroll 4
        for (int k = 0; k < ORIG; k++) {
            float w = ws[k*AA + tid];
            a0 += xs[k]*w; a1 += xs[ORIG+k]*w; a2 += xs[2*ORIG+k]*w; a3 += xs[3*ORIG+k]*w;
        }
        g_x[(n0+0)*AA + tid] = a0;
        g_x[(n0+1)*AA + tid] = a1;
        g_x[(n0+2)*AA + tid] = a2;
        g_x[(n0+3)*AA + tid] = a3;
        __syncthreads();
    }
}

// P1/P2 projection. 256 threads: t64 = col pair, r8 = row group (8 atoms each).
// NOTE: NN not divisible by 32 -> tail-guarded.
__global__ __launch_bounds__(256)
void k_proj(const float* __restrict__ w, const float* __restrict__ bias) {
    extern __shared__ float ws[];          // 128*128 floats = 64 KB
    __shared__ float xs[32*AA];            // 8 KB
    int tid = threadIdx.x;
    int t = tid & 63, r8 = tid >> 6;
    for (int i = tid; i < 128*TWOA; i += 256) ws[i] = w[i];
    __syncthreads();
    ull bc = f2x_pack(bias[2*t], bias[2*t+1]);
    const ull* wv = (const ull*)ws;
    const int NG = (NN + 31) / 32;         // 1563 (last group has 16 atoms)
    for (int g = blockIdx.x; g < NG; g += gridDim.x) {
        int n0 = g * 32;
        int cnt = min(32, NN - n0);
        for (int i = tid; i < cnt*AA; i += 256) xs[i] = g_x[(size_t)n0*AA + i];
        __syncthreads();
        const float* xb = &xs[r8*8*AA];
        int nb = n0 + r8*8;
        ull p1[8], p2[8];
        #pragma unroll
        for (int r = 0; r < 8; r++) { p1[r] = bc; p2[r] = 0ull; }
        #pragma unroll 4
        for (int a = 0; a < AA; a++) {
            ull w1 = wv[a*64 + t];
            ull w2 = wv[(AA+a)*64 + t];
            #pragma unroll
            for (int r = 0; r < 8; r++) {
                float xf = xb[r*AA + a];
                ull xv = f2x_pack(xf, xf);
                p1[r] = f2x_fma(xv, w1, p1[r]);
                p2[r] = f2x_fma(xv, w2, p2[r]);
            }
        }
        #pragma unroll
        for (int r = 0; r < 8; r++) {
            if (nb + r < NN) {
                ((ull*)&g_P1[(size_t)(nb+r)*TWOA])[t] = p1[r];
                ((ull*)&g_P2[(size_t)(nb+r)*TWOA])[t] = p2[r];
            }
        }
        __syncthreads();
    }
}

// gated = P1[n] + P2[nbr] + nbr_fea @ W_edge ; bn1 stats.
// chunk = 6 edge rows = half an atom (one P1 load per chunk).
__global__ __launch_bounds__(256, 4)
void k_edge(const float* __restrict__ we,       // 41x128
            const float* __restrict__ nbrf,     // (N,M,41)
            const int*   __restrict__ nidx) {   // (N,M)
    __shared__ ulonglong2 wsv[NBRD*32];    // 21 KB
    __shared__ float  nfs[8][6*NBRD + 2];  // ~7.9 KB
    __shared__ float  redS[TWOA], redQ[TWOA];
    int tid = threadIdx.x;
    {
        float* wf = (float*)wsv;
        for (int i = tid; i < NBRD*TWOA; i += 256) wf[i] = we[i];
    }
    __syncthreads();

    int w    = tid >> 5;
    int lane = tid & 31;
    int wg   = blockIdx.x * 8 + w;
    int nw   = gridDim.x * 8;

    ull s01 = 0ull, s23 = 0ull, q01 = 0ull, q23 = 0ull;

    const int NCH = RTOT/6;   // 100000
    for (int ch = wg; ch < NCH; ch += nw) {
        int r0 = ch * 6;
        int n  = ch >> 1;
        const float* src = &nbrf[(size_t)r0 * NBRD];
        #pragma unroll
        for (int i = 0; i < 8; i++) {
            int p = lane + i*32;
            if (p < 6*NBRD) nfs[w][p] = src[p];
        }
        __syncwarp();
        ulonglong2 pa = ((const ulonglong2*)&g_P1[(size_t)n*TWOA])[lane];
        ull a01[6], a23[6];
        #pragma unroll
        for (int rr = 0; rr < 6; rr++) {
            int j = nidx[r0 + rr];
            ulonglong2 pb = ((const ulonglong2*)&g_P2[(size_t)j*TWOA])[lane];
            a01[rr] = f2x_add(pa.x, pb.x);
            a23[rr] = f2x_add(pa.y, pb.y);
        }
        #pragma unroll 1
        for (int k = 0; k < NBRD; k++) {
            ulonglong2 wv = wsv[k*32 + lane];
            #pragma unroll
            for (int rr = 0; rr < 6; rr++) {
                float f = nfs[w][rr*NBRD + k];
                ull ff = f2x_pack(f, f);
                a01[rr] = f2x_fma(ff, wv.x, a01[rr]);
                a23[rr] = f2x_fma(ff, wv.y, a23[rr]);
            }
        }
        #pragma unroll
        for (int rr = 0; rr < 6; rr++) {
            ulonglong2 st; st.x = a01[rr]; st.y = a23[rr];
            *(ulonglong2*)&g_gated[(size_t)(r0+rr)*TWOA + lane*4] = st;
            s01 = f2x_add(s01, a01[rr]);
            s23 = f2x_add(s23, a23[rr]);
            q01 = f2x_fma(a01[rr], a01[rr], q01);
            q23 = f2x_fma(a23[rr], a23[rr], q23);
        }
        __syncwarp();
    }

    float s0,s1,s2,s3,q0,q1,q2,q3;
    f2x_unpack(s01, s0, s1); f2x_unpack(s23, s2, s3);
    f2x_unpack(q01, q0, q1); f2x_unpack(q23, q2, q3);

    if (tid < TWOA) { redS[tid] = 0.f; redQ[tid] = 0.f; }
    __syncthreads();
    int c = lane * 4;
    atomicAdd(&redS[c+0], s0); atomicAdd(&redQ[c+0], q0);
    atomicAdd(&redS[c+1], s1); atomicAdd(&redQ[c+1], q1);
    atomicAdd(&redS[c+2], s2); atomicAdd(&redQ[c+2], q2);
    atomicAdd(&redS[c+3], s3); atomicAdd(&redQ[c+3], q3);
    __syncthreads();
    if (tid < TWOA) {
        atomicAdd(&g_sum[tid],   (double)redS[tid]);
        atomicAdd(&g_sumsq[tid], (double)redQ[tid]);
    }
}

__global__ void k_bnstat(int ncols, double invR, int which,
                         const float* __restrict__ g, const float* __restrict__ b) {
    int t = threadIdx.x;
    if (t < ncols) {
        double s = g_sum[t], q = g_sumsq[t];
        double mean = s * invR;
        double var  = q * invR - mean * mean;
        float istd = rsqrtf((float)var + EPSB);
        float sc = istd * g[t];
        float sh = b[t] - (float)mean * sc;
        if (which == 1) { g_scale1[t] = sc; g_shift1[t] = sh; }
        else            { g_scale2[t] = sc; g_shift2[t] = sh; }
        g_sum[t] = 0.0; g_sumsq[t] = 0.0;
    }
}

// bn1 -> sigmoid*softplus -> sum over M -> summed ; bn2 stats
__global__ void k_apply() {
    int tx = threadIdx.x, ty = threadIdx.y;
    int c0 = tx * 2;
    float2 scF = *(const float2*)&g_scale1[c0];
    float2 shF = *(const float2*)&g_shift1[c0];
    float2 scC = *(const float2*)&g_scale1[AA + c0];
    float2 shC = *(const float2*)&g_shift1[AA + c0];
    float ls0=0.f, lq0=0.f, ls1=0.f, lq1=0.f;
    for (int n = blockIdx.x*8 + ty; n < NN; n += gridDim.x*8) {
        const float* gp = &g_gated[(size_t)n*(MM*TWOA)];
        float sx = 0.f, sy = 0.f;
        #pragma unroll
        for (int m = 0; m < MM; m++) {
            float2 fv = *(const float2*)&gp[m*TWOA + c0];
            float2 cv = *(const float2*)&gp[m*TWOA + AA + c0];
            float f0 = fv.x*scF.x + shF.x, c0v = cv.x*scC.x + shC.x;
            float f1 = fv.y*scF.y + shF.y, c1v = cv.y*scC.y + shC.y;
            sx += sigmoid_fast(f0) * softplus_fast(c0v);
            sy += sigmoid_fast(f1) * softplus_fast(c1v);
        }
        float2 out; out.x = sx; out.y = sy;
        *(float2*)&g_summed[(size_t)n*AA + c0] = out;
        ls0 += sx; lq0 += sx*sx; ls1 += sy; lq1 += sy*sy;
    }
    __shared__ float rS[AA], rQ[AA];
    if (ty == 0) { rS[c0]=0.f; rS[c0+1]=0.f; rQ[c0]=0.f; rQ[c0+1]=0.f; }
    __syncthreads();
    atomicAdd(&rS[c0],   ls0); atomicAdd(&rQ[c0],   lq0);
    atomicAdd(&rS[c0+1], ls1); atomicAdd(&rQ[c0+1], lq1);
    __syncthreads();
    if (ty == 0) {
        atomicAdd(&g_sum[c0],     (double)rS[c0]);
        atomicAdd(&g_sumsq[c0],   (double)rQ[c0]);
        atomicAdd(&g_sum[c0+1],   (double)rS[c0+1]);
        atomicAdd(&g_sumsq[c0+1], (double)rQ[c0+1]);
    }
}

__global__ void k_update() {
    int idx = blockIdx.x * blockDim.x + threadIdx.x;
    if (idx >= NN*AA) return;
    int a = idx & (AA-1);
    float v = g_x[idx] + g_summed[idx] * g_scale2[a] + g_shift2[a];
    g_x[idx] = softplus_fast(v);
}

// Final stage: warp owns groups of 4 atoms. 512 threads/block.
__global__ __launch_bounds__(512)
void k_final(const int* __restrict__ cidx,
             const float* __restrict__ adjw, const float* __restrict__ adjb,
             const float* __restrict__ fc1w, const float* __restrict__ fc1b,
             const float* __restrict__ afw,  const float* __restrict__ afb,
             float* __restrict__ out2) {
    extern __shared__ float smem[];
    float* Wt   = smem;                    // 24576 floats  Wt[o][e][d] = adjw[o][d][e]
    float* afws = Wt + 6*64*64;            // 5888
    float* vst  = afws + AA*ORIG;          // 16*4*64
    float* qsh  = vst + 16*4*64;           // 16*4*6
    int tid = threadIdx.x;
    int w = tid >> 5, lane = tid & 31;
    for (int i = tid; i < 6*64*64; i += 512) {
        int o = i >> 12, rem = i & 4095, e = rem >> 6, d = rem & 63;
        Wt[i] = adjw[o*4096 + d*64 + e];
    }
    for (int i = tid; i < AA*ORIG; i += 512) afws[i] = afw[i];
    __syncthreads();

    float* vw = &vst[w*4*64];
    float* qw = &qsh[w*4*6];
    ull bias0 = *(const ull*)&afb[2*lane];
    ull bias1 = (lane < 14) ? *(const ull*)&afb[64 + 2*lane] : 0ull;

    int nwarps = gridDim.x * 16;
    int wgid   = blockIdx.x * 16 + w;
    for (int g0 = wgid*4; g0 < BB*NPCC; g0 += nwarps*4) {
        #pragma unroll
        for (int t = 0; t < 4; t++) {
            int idx = cidx[g0 + t];
            vw[t*64 + lane]      = g_x[(size_t)idx*AA + lane];
            vw[t*64 + lane + 32] = g_x[(size_t)idx*AA + lane + 32];
        }
        __syncwarp();
        float2 rv[4];
        #pragma unroll
        for (int t = 0; t < 4; t++) rv[t] = *(const float2*)&vw[t*64 + 2*lane];

        ull acc[4][6];
        #pragma unroll
        for (int t = 0; t < 4; t++)
            #pragma unroll
            for (int o = 0; o < 6; o++) acc[t][o] = 0ull;
        #pragma unroll 2
        for (int e = 0; e < 64; e++) {
            ull wv[6];
            #pragma unroll
            for (int o = 0; o < 6; o++) wv[o] = *(const ull*)&Wt[(o*64 + e)*64 + 2*lane];
            #pragma unroll
            for (int t = 0; t < 4; t++) {
                float vb = vw[t*64 + e];
                ull vbb = f2x_pack(vb, vb);
                #pragma unroll
                for (int o = 0; o < 6; o++) acc[t][o] = f2x_fma(vbb, wv[o], acc[t][o]);
            }
        }
        #pragma unroll
        for (int t = 0; t < 4; t++) {
            #pragma unroll
            for (int o = 0; o < 6; o++) {
                float lo, hi; f2x_unpack(acc[t][o], lo, hi);
                float p = lo * rv[t].x + hi * rv[t].y;
                #pragma unroll
                for (int off = 16; off; off >>= 1) p += __shfl_xor_sync(0xffffffffu, p, off);
                if (lane == 0) qw[t*6 + o] = p + adjb[o];
            }
        }
        __syncwarp();
        if (lane < 4) {
            int t = lane;
            float q[6], q2[6];
            #pragma unroll
            for (int o = 0; o < 6; o++) q[o] = qw[t*6 + o];
            #pragma unroll
            for (int j = 0; j < 6; j++) {
                float a = fc1b[j];
                #pragma unroll
                for (int o = 0; o < 6; o++) a += q[o] * fc1w[o*6 + j];
                q2[j] = a;
            }
            float mx = q2[0];
            #pragma unroll
            for (int j = 1; j < 6; j++) mx = fmaxf(mx, q2[j]);
            float se = 0.f;
            #pragma unroll
            for (int j = 0; j < 6; j++) se += __expf(q2[j] - mx);
            float lse = __logf(se);
            #pragma unroll
            for (int j = 0; j < 6; j++) g_logp[(g0 + t)*6 + j] = q2[j] - mx - lse;
        }
        {
            ull acc0[4], acc1[4];
            #pragma unroll
            for (int t = 0; t < 4; t++) { acc0[t] = bias0; acc1[t] = bias1; }
            #pragma unroll 2
            for (int a = 0; a < 64; a++) {
                ull w0 = *(const ull*)&afws[a*ORIG + 2*lane];
                ull w1 = (lane < 14) ? *(const ull*)&afws[a*ORIG + 64 + 2*lane] : 0ull;
                #pragma unroll
                for (int t = 0; t < 4; t++) {
                    float va = vw[t*64 + a];
                    ull vv = f2x_pack(va, va);
                    acc0[t] = f2x_fma(vv, w0, acc0[t]);
                    acc1[t] = f2x_fma(vv, w1, acc1[t]);
                }
            }
            #pragma unroll
            for (int t = 0; t < 4; t++) {
                *(ull*)&out2[(size_t)(g0+t)*ORIG + 2*lane] = acc0[t];
                if (lane < 14) *(ull*)&out2[(size_t)(g0+t)*ORIG + 64 + 2*lane] = acc1[t];
            }
        }
        __syncwarp();
    }
}

// edge_prob broadcast
__global__ void k_edgeprob(float* __restrict__ out) {
    __shared__ float sh[NPCC*6];
    int b = blockIdx.x;
    for (int i = threadIdx.x; i < NPCC*6; i += 256) sh[i] = g_logp[b*NPCC*6 + i];
    __syncthreads();
    float* o = out + (size_t)b * (NPCC*NPCC*6);
    for (int t = threadIdx.x; t < NPCC*NPCC*6; t += 256) o[t] = sh[t % (NPCC*6)];
}

// ---------------- host ----------------
extern "C" void kernel_launch(void* const* d_in, const int* in_sizes, int n_in,
                              void* d_out, int out_size) {
    const float* atom_fea = (const float*)d_in[0];
    const float* nbr_fea  = (const float*)d_in[1];
    const int*   nbr_idx  = (const int*)  d_in[2];
    const int*   cidx     = (const int*)  d_in[3];
    const float* emb_w    = (const float*)d_in[4];
    const float* fcw      = (const float*)d_in[5];
    const float* fcb      = (const float*)d_in[6];
    const float* bn1g     = (const float*)d_in[7];
    const float* bn1b     = (const float*)d_in[8];
    const float* bn2g     = (const float*)d_in[9];
    const float* bn2b     = (const float*)d_in[10];
    const float* adjw     = (const float*)d_in[11];
    const float* adjb     = (const float*)d_in[12];
    const float* fc1w     = (const float*)d_in[13];
    const float* fc1b     = (const float*)d_in[14];
    const float* afw      = (const float*)d_in[15];
    const float* afb      = (const float*)d_in[16];
    float* out = (float*)d_out;

    const int PROJ_SMEM  = 128 * TWOA * sizeof(float);                             // 64 KB
    const int FINAL_SMEM = (6*64*64 + AA*ORIG + 16*4*64 + 16*4*6) * sizeof(float); // ~136.5 KB
    cudaFuncSetAttribute(k_proj,  cudaFuncAttributeMaxDynamicSharedMemorySize, PROJ_SMEM);
    cudaFuncSetAttribute(k_final, cudaFuncAttributeMaxDynamicSharedMemorySize, FINAL_SMEM);

    k_zero_stats<<<1, 256>>>();
    k_embed<<<1184, 64>>>(atom_fea, emb_w);

    for (int i = 0; i < 3; i++) {
        const float* w = fcw + i * (2*AA + NBRD) * TWOA;
        k_proj<<<444, 256, PROJ_SMEM>>>(w, fcb + i*TWOA);
        k_edge<<<592, 256>>>(w + 2*AA*TWOA, nbr_fea, nbr_idx);
        k_bnstat<<<1, 128>>>(TWOA, 1.0 / (double)RTOT, 1, bn1g + i*TWOA, bn1b + i*TWOA);
        k_apply<<<1184, dim3(32, 8)>>>();
        k_bnstat<<<1, 128>>>(AA, 1.0 / (double)NN, 2, bn2g + i*AA, bn2b + i*AA);
        k_update<<<(NN*AA + 255)/256, 256>>>();
    }

    float* out_atomfea = out + (size_t)BB * NPCC * NPCC * 6;
    k_final<<<148, 512, FINAL_SMEM>>>(cidx, adjw, adjb, fc1w, fc1b, afw, afb, out_atomfea);
    k_edgeprob<<<BB, 256>>>(out);
}

// round 5
// speedup vs baseline: 2.2622x; 1.0351x over previous
#include <cuda_runtime.h>
#include <math.h>

#define NN 50000
#define MM 12
#define AA 64
#define NBRD 41
#define TWOA 128
#define BB 1000
#define NPCC 50
#define ORIG 92
#define RTOT (NN*MM)          // 600000 edge rows
#define EPSB 1e-5f
#define NFS_STRIDE 44         // padded row stride for f4 loads

typedef unsigned long long ull;

// ---------------- device scratch ----------------
__device__ float  g_x[NN*AA];
__device__ float  g_summed[NN*AA];
__device__ float  g_P1[NN*TWOA];
__device__ float  g_P2[NN*TWOA];
__device__ float  g_gated[RTOT*TWOA];         // 307 MB
__device__ double g_sum[TWOA];
__device__ double g_sumsq[TWOA];
__device__ float  g_scale1[TWOA], g_shift1[TWOA];
__device__ float  g_scale2[AA],   g_shift2[AA];
__device__ float  g_logp[BB*NPCC*6];

// ---------------- f32x2 helpers ----------------
__device__ __forceinline__ ull f2x_pack(float lo, float hi) {
    ull r; asm("mov.b64 %0, {%1, %2};" : "=l"(r) : "f"(lo), "f"(hi)); return r;
}
__device__ __forceinline__ void f2x_unpack(ull v, float& lo, float& hi) {
    asm("mov.b64 {%0, %1}, %2;" : "=f"(lo), "=f"(hi) : "l"(v));
}
__device__ __forceinline__ ull f2x_fma(ull a, ull b, ull c) {
    ull d; asm("fma.rn.f32x2 %0, %1, %2, %3;" : "=l"(d) : "l"(a), "l"(b), "l"(c)); return d;
}
__device__ __forceinline__ ull f2x_add(ull a, ull b) {
    ull d; asm("add.rn.f32x2 %0, %1, %2;" : "=l"(d) : "l"(a), "l"(b)); return d;
}

// ---------------- fast math ----------------
__device__ __forceinline__ float softplus_fast(float x) {
    return fmaxf(x, 0.0f) + __logf(1.0f + __expf(-fabsf(x)));
}
__device__ __forceinline__ float sigmoid_fast(float x) {
    return __fdividef(1.0f, 1.0f + __expf(-x));
}

// ---------------- kernels ----------------
__global__ void k_zero_stats() {
    int t = threadIdx.x;
    if (t < TWOA) { g_sum[t] = 0.0; g_sumsq[t] = 0.0; }
}

// x = atom_fea @ emb_w   (50000x92)@(92x64) — 256 threads, 16 atoms/iter
__global__ __launch_bounds__(256)
void k_embed(const float* __restrict__ afea, const float* __restrict__ embw) {
    __shared__ float ws[ORIG*AA];      // 23.5 KB
    __shared__ float xs[16*ORIG];      // 5.9 KB
    int tid = threadIdx.x;
    int t = tid & 63, r4 = tid >> 6;   // col, row-group of 4
    for (int i = tid; i < ORIG*AA; i += 256) ws[i] = embw[i];
    __syncthreads();
    const int NG = NN / 16;            // 3125 exact
    for (int g = blockIdx.x; g < NG; g += gridDim.x) {
        int n0 = g * 16;
        for (int i = tid; i < 16*ORIG; i += 256) xs[i] = afea[(size_t)n0*ORIG + i];
        __syncthreads();
        const float* xb = &xs[r4*4*ORIG];
        float a0 = 0.f, a1 = 0.f, a2 = 0.f, a3 = 0.f;
        #pragma unroll 4
        for (int k = 0; k < ORIG; k++) {
            float w = ws[k*AA + t];
            a0 += xb[k]*w; a1 += xb[ORIG+k]*w; a2 += xb[2*ORIG+k]*w; a3 += xb[3*ORIG+k]*w;
        }
        int nb = n0 + r4*4;
        g_x[(size_t)(nb+0)*AA + t] = a0;
        g_x[(size_t)(nb+1)*AA + t] = a1;
        g_x[(size_t)(nb+2)*AA + t] = a2;
        g_x[(size_t)(nb+3)*AA + t] = a3;
        __syncthreads();
    }
}

// P1/P2 projection. 256 threads: t64 = col pair, r8 = row group (8 atoms each).
__global__ __launch_bounds__(256)
void k_proj(const float* __restrict__ w, const float* __restrict__ bias) {
    extern __shared__ float ws[];          // 128*128 floats = 64 KB
    __shared__ float xs[32*AA];            // 8 KB
    int tid = threadIdx.x;
    int t = tid & 63, r8 = tid >> 6;
    for (int i = tid; i < 128*TWOA; i += 256) ws[i] = w[i];
    __syncthreads();
    ull bc = f2x_pack(bias[2*t], bias[2*t+1]);
    const ull* wv = (const ull*)ws;
    const int NG = (NN + 31) / 32;         // tail-guarded
    for (int g = blockIdx.x; g < NG; g += gridDim.x) {
        int n0 = g * 32;
        int cnt = min(32, NN - n0);
        for (int i = tid; i < cnt*AA; i += 256) xs[i] = g_x[(size_t)n0*AA + i];
        __syncthreads();
        const float* xb = &xs[r8*8*AA];
        int nb = n0 + r8*8;
        ull p1[8], p2[8];
        #pragma unroll
        for (int r = 0; r < 8; r++) { p1[r] = bc; p2[r] = 0ull; }
        #pragma unroll 4
        for (int a = 0; a < AA; a++) {
            ull w1 = wv[a*64 + t];
            ull w2 = wv[(AA+a)*64 + t];
            #pragma unroll
            for (int r = 0; r < 8; r++) {
                float xf = xb[r*AA + a];
                ull xv = f2x_pack(xf, xf);
                p1[r] = f2x_fma(xv, w1, p1[r]);
                p2[r] = f2x_fma(xv, w2, p2[r]);
            }
        }
        #pragma unroll
        for (int r = 0; r < 8; r++) {
            if (nb + r < NN) {
                ((ull*)&g_P1[(size_t)(nb+r)*TWOA])[t] = p1[r];
                ((ull*)&g_P2[(size_t)(nb+r)*TWOA])[t] = p2[r];
            }
        }
        __syncthreads();
    }
}

// gated = P1[n] + P2[nbr] + nbr_fea @ W_edge ; bn1 stats.
// chunk = 6 edge rows; k-blocked (4) with broadcast float4 f loads from padded smem.
__global__ __launch_bounds__(256, 3)
void k_edge(const float* __restrict__ we,       // 41x128
            const float* __restrict__ nbrf,     // (N,M,41)
            const int*   __restrict__ nidx) {   // (N,M)
    __shared__ ulonglong2 wsv[NBRD*32];          // 21 KB
    __shared__ float  nfs[8][6*NFS_STRIDE];      // 8 × 264 floats = 8.25 KB
    __shared__ float  redS[TWOA], redQ[TWOA];
    int tid = threadIdx.x;
    {
        float* wf = (float*)wsv;
        for (int i = tid; i < NBRD*TWOA; i += 256) wf[i] = we[i];
    }
    __syncthreads();

    int w    = tid >> 5;
    int lane = tid & 31;
    int wg   = blockIdx.x * 8 + w;
    int nw   = gridDim.x * 8;

    ull s01 = 0ull, s23 = 0ull, q01 = 0ull, q23 = 0ull;

    const int NCH = RTOT/6;   // 100000
    for (int ch = wg; ch < NCH; ch += nw) {
        int r0 = ch * 6;
        int n  = ch >> 1;
        const float* src = &nbrf[(size_t)r0 * NBRD];
        #pragma unroll
        for (int i = 0; i < 8; i++) {
            int p = lane + i*32;
            if (p < 6*NBRD) {
                int rr = p / NBRD, kk = p - rr*NBRD;
                nfs[w][rr*NFS_STRIDE + kk] = src[p];
            }
        }
        __syncwarp();
        ulonglong2 pa = ((const ulonglong2*)&g_P1[(size_t)n*TWOA])[lane];
        ull a01[6], a23[6];
        #pragma unroll
        for (int rr = 0; rr < 6; rr++) {
            int j = nidx[r0 + rr];
            ulonglong2 pb = ((const ulonglong2*)&g_P2[(size_t)j*TWOA])[lane];
            a01[rr] = f2x_add(pa.x, pb.x);
            a23[rr] = f2x_add(pa.y, pb.y);
        }
        #pragma unroll 1
        for (int kb = 0; kb < 40; kb += 4) {
            ulonglong2 w0 = wsv[(kb+0)*32 + lane];
            ulonglong2 w1 = wsv[(kb+1)*32 + lane];
            ulonglong2 w2 = wsv[(kb+2)*32 + lane];
            ulonglong2 w3 = wsv[(kb+3)*32 + lane];
            #pragma unroll
            for (int rr = 0; rr < 6; rr++) {
                float4 f = *(const float4*)&nfs[w][rr*NFS_STRIDE + kb];
                ull fx = f2x_pack(f.x, f.x);
                ull fy = f2x_pack(f.y, f.y);
                ull fz = f2x_pack(f.z, f.z);
                ull fw = f2x_pack(f.w, f.w);
                a01[rr] = f2x_fma(fx, w0.x, a01[rr]); a23[rr] = f2x_fma(fx, w0.y, a23[rr]);
                a01[rr] = f2x_fma(fy, w1.x, a01[rr]); a23[rr] = f2x_fma(fy, w1.y, a23[rr]);
                a01[rr] = f2x_fma(fz, w2.x, a01[rr]); a23[rr] = f2x_fma(fz, w2.y, a23[rr]);
                a01[rr] = f2x_fma(fw, w3.x, a01[rr]); a23[rr] = f2x_fma(fw, w3.y, a23[rr]);
            }
        }
        {   // remainder k = 40
            ulonglong2 w4 = wsv[40*32 + lane];
            #pragma unroll
            for (int rr = 0; rr < 6; rr++) {
                float f = nfs[w][rr*NFS_STRIDE + 40];
                ull ff = f2x_pack(f, f);
                a01[rr] = f2x_fma(ff, w4.x, a01[rr]);
                a23[rr] = f2x_fma(ff, w4.y, a23[rr]);
            }
        }
        #pragma unroll
        for (int rr = 0; rr < 6; rr++) {
            ulonglong2 st; st.x = a01[rr]; st.y = a23[rr];
            *(ulonglong2*)&g_gated[(size_t)(r0+rr)*TWOA + lane*4] = st;
            s01 = f2x_add(s01, a01[rr]);
            s23 = f2x_add(s23, a23[rr]);
            q01 = f2x_fma(a01[rr], a01[rr], q01);
            q23 = f2x_fma(a23[rr], a23[rr], q23);
        }
        __syncwarp();
    }

    float s0,s1,s2,s3,q0,q1,q2,q3;
    f2x_unpack(s01, s0, s1); f2x_unpack(s23, s2, s3);
    f2x_unpack(q01, q0, q1); f2x_unpack(q23, q2, q3);

    if (tid < TWOA) { redS[tid] = 0.f; redQ[tid] = 0.f; }
    __syncthreads();
    int c = lane * 4;
    atomicAdd(&redS[c+0], s0); atomicAdd(&redQ[c+0], q0);
    atomicAdd(&redS[c+1], s1); atomicAdd(&redQ[c+1], q1);
    atomicAdd(&redS[c+2], s2); atomicAdd(&redQ[c+2], q2);
    atomicAdd(&redS[c+3], s3); atomicAdd(&redQ[c+3], q3);
    __syncthreads();
    if (tid < TWOA) {
        atomicAdd(&g_sum[tid],   (double)redS[tid]);
        atomicAdd(&g_sumsq[tid], (double)redQ[tid]);
    }
}

__global__ void k_bnstat(int ncols, double invR, int which,
                         const float* __restrict__ g, const float* __restrict__ b) {
    int t = threadIdx.x;
    if (t < ncols) {
        double s = g_sum[t], q = g_sumsq[t];
        double mean = s * invR;
        double var  = q * invR - mean * mean;
        float istd = rsqrtf((float)var + EPSB);
        float sc = istd * g[t];
        float sh = b[t] - (float)mean * sc;
        if (which == 1) { g_scale1[t] = sc; g_shift1[t] = sh; }
        else            { g_scale2[t] = sc; g_shift2[t] = sh; }
        g_sum[t] = 0.0; g_sumsq[t] = 0.0;
    }
}

// bn1 -> sigmoid*softplus -> sum over M -> summed ; bn2 stats.
// 256 threads: tx(16) = col quad, ty(16) = atom.
__global__ __launch_bounds__(256)
void k_apply() {
    int tid = threadIdx.x;
    int tx = tid & 15, ty = tid >> 4;
    int c0 = tx * 4;
    float4 scF = *(const float4*)&g_scale1[c0];
    float4 shF = *(const float4*)&g_shift1[c0];
    float4 scC = *(const float4*)&g_scale1[AA + c0];
    float4 shC = *(const float4*)&g_shift1[AA + c0];
    float ls0=0,ls1=0,ls2=0,ls3=0, lq0=0,lq1=0,lq2=0,lq3=0;
    for (int n = blockIdx.x*16 + ty; n < NN; n += gridDim.x*16) {
        const float4* gp = (const float4*)&g_gated[(size_t)n*(MM*TWOA)];
        float s0=0,s1=0,s2=0,s3=0;
        #pragma unroll
        for (int m = 0; m < MM; m++) {
            float4 fv = gp[m*32 + tx];
            float4 cv = gp[m*32 + 16 + tx];
            s0 += sigmoid_fast(fv.x*scF.x + shF.x) * softplus_fast(cv.x*scC.x + shC.x);
            s1 += sigmoid_fast(fv.y*scF.y + shF.y) * softplus_fast(cv.y*scC.y + shC.y);
            s2 += sigmoid_fast(fv.z*scF.z + shF.z) * softplus_fast(cv.z*scC.z + shC.z);
            s3 += sigmoid_fast(fv.w*scF.w + shF.w) * softplus_fast(cv.w*scC.w + shC.w);
        }
        float4 outv; outv.x=s0; outv.y=s1; outv.z=s2; outv.w=s3;
        *(float4*)&g_summed[(size_t)n*AA + c0] = outv;
        ls0+=s0; lq0+=s0*s0; ls1+=s1; lq1+=s1*s1;
        ls2+=s2; lq2+=s2*s2; ls3+=s3; lq3+=s3*s3;
    }
    __shared__ float rS[AA], rQ[AA];
    if (ty == 0) {
        #pragma unroll
        for (int i = 0; i < 4; i++) { rS[c0+i] = 0.f; rQ[c0+i] = 0.f; }
    }
    __syncthreads();
    atomicAdd(&rS[c0+0], ls0); atomicAdd(&rQ[c0+0], lq0);
    atomicAdd(&rS[c0+1], ls1); atomicAdd(&rQ[c0+1], lq1);
    atomicAdd(&rS[c0+2], ls2); atomicAdd(&rQ[c0+2], lq2);
    atomicAdd(&rS[c0+3], ls3); atomicAdd(&rQ[c0+3], lq3);
    __syncthreads();
    if (ty == 0) {
        #pragma unroll
        for (int i = 0; i < 4; i++) {
            atomicAdd(&g_sum[c0+i],   (double)rS[c0+i]);
            atomicAdd(&g_sumsq[c0+i], (double)rQ[c0+i]);
        }
    }
}

__global__ void k_update() {
    int idx = blockIdx.x * blockDim.x + threadIdx.x;
    if (idx >= NN*AA) return;
    int a = idx & (AA-1);
    float v = g_x[idx] + g_summed[idx] * g_scale2[a] + g_shift2[a];
    g_x[idx] = softplus_fast(v);
}

// Final stage: warp owns groups of 4 atoms. 512 threads/block.
__global__ __launch_bounds__(512)
void k_final(const int* __restrict__ cidx,
             const float* __restrict__ adjw, const float* __restrict__ adjb,
             const float* __restrict__ fc1w, const float* __restrict__ fc1b,
             const float* __restrict__ afw,  const float* __restrict__ afb,
             float* __restrict__ out2) {
    extern __shared__ float smem[];
    float* Wt   = smem;                    // Wt[o][e][d] = adjw[o][d][e]
    float* afws = Wt + 6*64*64;
    float* vst  = afws + AA*ORIG;
    float* qsh  = vst + 16*4*64;
    int tid = threadIdx.x;
    int w = tid >> 5, lane = tid & 31;
    for (int i = tid; i < 6*64*64; i += 512) {
        int o = i >> 12, rem = i & 4095, e = rem >> 6, d = rem & 63;
        Wt[i] = adjw[o*4096 + d*64 + e];
    }
    for (int i = tid; i < AA*ORIG; i += 512) afws[i] = afw[i];
    __syncthreads();

    float* vw = &vst[w*4*64];
    float* qw = &qsh[w*4*6];
    ull bias0 = *(const ull*)&afb[2*lane];
    ull bias1 = (lane < 14) ? *(const ull*)&afb[64 + 2*lane] : 0ull;

    int nwarps = gridDim.x * 16;
    int wgid   = blockIdx.x * 16 + w;
    for (int g0 = wgid*4; g0 < BB*NPCC; g0 += nwarps*4) {
        #pragma unroll
        for (int t = 0; t < 4; t++) {
            int idx = cidx[g0 + t];
            vw[t*64 + lane]      = g_x[(size_t)idx*AA + lane];
            vw[t*64 + lane + 32] = g_x[(size_t)idx*AA + lane + 32];
        }
        __syncwarp();
        float2 rv[4];
        #pragma unroll
        for (int t = 0; t < 4; t++) rv[t] = *(const float2*)&vw[t*64 + 2*lane];

        ull acc[4][6];
        #pragma unroll
        for (int t = 0; t < 4; t++)
            #pragma unroll
            for (int o = 0; o < 6; o++) acc[t][o] = 0ull;
        #pragma unroll 2
        for (int e = 0; e < 64; e++) {
            ull wv[6];
            #pragma unroll
            for (int o = 0; o < 6; o++) wv[o] = *(const ull*)&Wt[(o*64 + e)*64 + 2*lane];
            #pragma unroll
            for (int t = 0; t < 4; t++) {
                float vb = vw[t*64 + e];
                ull vbb = f2x_pack(vb, vb);
                #pragma unroll
                for (int o = 0; o < 6; o++) acc[t][o] = f2x_fma(vbb, wv[o], acc[t][o]);
            }
        }
        #pragma unroll
        for (int t = 0; t < 4; t++) {
            #pragma unroll
            for (int o = 0; o < 6; o++) {
                float lo, hi; f2x_unpack(acc[t][o], lo, hi);
                float p = lo * rv[t].x + hi * rv[t].y;
                #pragma unroll
                for (int off = 16; off; off >>= 1) p += __shfl_xor_sync(0xffffffffu, p, off);
                if (lane == 0) qw[t*6 + o] = p + adjb[o];
            }
        }
        __syncwarp();
        if (lane < 4) {
            int t = lane;
            float q[6], q2[6];
            #pragma unroll
            for (int o = 0; o < 6; o++) q[o] = qw[t*6 + o];
            #pragma unroll
            for (int j = 0; j < 6; j++) {
                float a = fc1b[j];
                #pragma unroll
                for (int o = 0; o < 6; o++) a += q[o] * fc1w[o*6 + j];
                q2[j] = a;
            }
            float mx = q2[0];
            #pragma unroll
            for (int j = 1; j < 6; j++) mx = fmaxf(mx, q2[j]);
            float se = 0.f;
            #pragma unroll
            for (int j = 0; j < 6; j++) se += __expf(q2[j] - mx);
            float lse = __logf(se);
            #pragma unroll
            for (int j = 0; j < 6; j++) g_logp[(g0 + t)*6 + j] = q2[j] - mx - lse;
        }
        {
            ull acc0[4], acc1[4];
            #pragma unroll
            for (int t = 0; t < 4; t++) { acc0[t] = bias0; acc1[t] = bias1; }
            #pragma unroll 2
            for (int a = 0; a < 64; a++) {
                ull w0 = *(const ull*)&afws[a*ORIG + 2*lane];
                ull w1 = (lane < 14) ? *(const ull*)&afws[a*ORIG + 64 + 2*lane] : 0ull;
                #pragma unroll
                for (int t = 0; t < 4; t++) {
                    float va = vw[t*64 + a];
                    ull vv = f2x_pack(va, va);
                    acc0[t] = f2x_fma(vv, w0, acc0[t]);
                    acc1[t] = f2x_fma(vv, w1, acc1[t]);
                }
            }
            #pragma unroll
            for (int t = 0; t < 4; t++) {
                *(ull*)&out2[(size_t)(g0+t)*ORIG + 2*lane] = acc0[t];
                if (lane < 14) *(ull*)&out2[(size_t)(g0+t)*ORIG + 64 + 2*lane] = acc1[t];
            }
        }
        __syncwarp();
    }
}

// edge_prob broadcast
__global__ void k_edgeprob(float* __restrict__ out) {
    __shared__ float sh[NPCC*6];
    int b = blockIdx.x;
    for (int i = threadIdx.x; i < NPCC*6; i += 256) sh[i] = g_logp[b*NPCC*6 + i];
    __syncthreads();
    float* o = out + (size_t)b * (NPCC*NPCC*6);
    for (int t = threadIdx.x; t < NPCC*NPCC*6; t += 256) o[t] = sh[t % (NPCC*6)];
}

// ---------------- host ----------------
extern "C" void kernel_launch(void* const* d_in, const int* in_sizes, int n_in,
                              void* d_out, int out_size) {
    const float* atom_fea = (const float*)d_in[0];
    const float* nbr_fea  = (const float*)d_in[1];
    const int*   nbr_idx  = (const int*)  d_in[2];
    const int*   cidx     = (const int*)  d_in[3];
    const float* emb_w    = (const float*)d_in[4];
    const float* fcw      = (const float*)d_in[5];
    const float* fcb      = (const float*)d_in[6];
    const float* bn1g     = (const float*)d_in[7];
    const float* bn1b     = (const float*)d_in[8];
    const float* bn2g     = (const float*)d_in[9];
    const float* bn2b     = (const float*)d_in[10];
    const float* adjw     = (const float*)d_in[11];
    const float* adjb     = (const float*)d_in[12];
    const float* fc1w     = (const float*)d_in[13];
    const float* fc1b     = (const float*)d_in[14];
    const float* afw      = (const float*)d_in[15];
    const float* afb      = (const float*)d_in[16];
    float* out = (float*)d_out;

    const int PROJ_SMEM  = 128 * TWOA * sizeof(float);                             // 64 KB
    const int FINAL_SMEM = (6*64*64 + AA*ORIG + 16*4*64 + 16*4*6) * sizeof(float); // ~136.5 KB
    cudaFuncSetAttribute(k_proj,  cudaFuncAttributeMaxDynamicSharedMemorySize, PROJ_SMEM);
    cudaFuncSetAttribute(k_final, cudaFuncAttributeMaxDynamicSharedMemorySize, FINAL_SMEM);

    k_zero_stats<<<1, 256>>>();
    k_embed<<<1184, 256>>>(atom_fea, emb_w);

    for (int i = 0; i < 3; i++) {
        const float* w = fcw + i * (2*AA + NBRD) * TWOA;
        k_proj<<<444, 256, PROJ_SMEM>>>(w, fcb + i*TWOA);
        k_edge<<<444, 256>>>(w + 2*AA*TWOA, nbr_fea, nbr_idx);
        k_bnstat<<<1, 128>>>(TWOA, 1.0 / (double)RTOT, 1, bn1g + i*TWOA, bn1b + i*TWOA);
        k_apply<<<1184, 256>>>();
        k_bnstat<<<1, 128>>>(AA, 1.0 / (double)NN, 2, bn2g + i*AA, bn2b + i*AA);
        k_update<<<(NN*AA + 255)/256, 256>>>();
    }

    float* out_atomfea = out + (size_t)BB * NPCC * NPCC * 6;
    k_final<<<148, 512, FINAL_SMEM>>>(cidx, adjw, adjb, fc1w, fc1b, afw, afb, out_atomfea);
    k_edgeprob<<<BB, 256>>>(out);
}

// round 6
// speedup vs baseline: 2.4733x; 1.0933x over previous
#include <cuda_runtime.h>
#include <cuda_fp16.h>
#include <math.h>

#define NN 50000
#define MM 12
#define AA 64
#define NBRD 41
#define TWOA 128
#define BB 1000
#define NPCC 50
#define ORIG 92
#define RTOT (NN*MM)          // 600000 edge rows
#define EPSB 1e-5f
#define NFS_STRIDE 44

typedef unsigned long long ull;

// ---------------- device scratch ----------------
__device__ float  g_x[NN*AA];
__device__ float  g_summed[NN*AA];
__device__ float  g_P1[NN*TWOA];
__device__ float  g_P2[NN*TWOA];
__device__ __half g_gatedh[(size_t)RTOT*TWOA];   // 153 MB fp16
__device__ double g_sum1[3][TWOA], g_sumsq1[3][TWOA];
__device__ double g_sum2[3][AA],   g_sumsq2[3][AA];
__device__ float  g_logp[BB*NPCC*6];

// ---------------- f32x2 helpers ----------------
__device__ __forceinline__ ull f2x_pack(float lo, float hi) {
    ull r; asm("mov.b64 %0, {%1, %2};" : "=l"(r) : "f"(lo), "f"(hi)); return r;
}
__device__ __forceinline__ void f2x_unpack(ull v, float& lo, float& hi) {
    asm("mov.b64 {%0, %1}, %2;" : "=f"(lo), "=f"(hi) : "l"(v));
}
__device__ __forceinline__ ull f2x_fma(ull a, ull b, ull c) {
    ull d; asm("fma.rn.f32x2 %0, %1, %2, %3;" : "=l"(d) : "l"(a), "l"(b), "l"(c)); return d;
}
__device__ __forceinline__ ull f2x_add(ull a, ull b) {
    ull d; asm("add.rn.f32x2 %0, %1, %2;" : "=l"(d) : "l"(a), "l"(b)); return d;
}

// ---------------- fast math ----------------
__device__ __forceinline__ float softplus_fast(float x) {
    return fmaxf(x, 0.0f) + __logf(1.0f + __expf(-fabsf(x)));
}
__device__ __forceinline__ float sigmoid_fast(float x) {
    return __fdividef(1.0f, 1.0f + __expf(-x));
}

// ---------------- kernels ----------------
__global__ void k_zero_stats() {
    int t = threadIdx.x;
    for (int i = t; i < 3*TWOA; i += 256) { (&g_sum1[0][0])[i] = 0.0; (&g_sumsq1[0][0])[i] = 0.0; }
    for (int i = t; i < 3*AA;   i += 256) { (&g_sum2[0][0])[i] = 0.0; (&g_sumsq2[0][0])[i] = 0.0; }
}

// x = atom_fea @ emb_w
__global__ __launch_bounds__(256)
void k_embed(const float* __restrict__ afea, const float* __restrict__ embw) {
    __shared__ float ws[ORIG*AA];
    __shared__ float xs[16*ORIG];
    int tid = threadIdx.x;
    int t = tid & 63, r4 = tid >> 6;
    for (int i = tid; i < ORIG*AA; i += 256) ws[i] = embw[i];
    __syncthreads();
    const int NG = NN / 16;
    for (int g = blockIdx.x; g < NG; g += gridDim.x) {
        int n0 = g * 16;
        for (int i = tid; i < 16*ORIG; i += 256) xs[i] = afea[(size_t)n0*ORIG + i];
        __syncthreads();
        const float* xb = &xs[r4*4*ORIG];
        float a0 = 0.f, a1 = 0.f, a2 = 0.f, a3 = 0.f;
        #pragma unroll 4
        for (int k = 0; k < ORIG; k++) {
            float w = ws[k*AA + t];
            a0 += xb[k]*w; a1 += xb[ORIG+k]*w; a2 += xb[2*ORIG+k]*w; a3 += xb[3*ORIG+k]*w;
        }
        int nb = n0 + r4*4;
        g_x[(size_t)(nb+0)*AA + t] = a0;
        g_x[(size_t)(nb+1)*AA + t] = a1;
        g_x[(size_t)(nb+2)*AA + t] = a2;
        g_x[(size_t)(nb+3)*AA + t] = a3;
        __syncthreads();
    }
}

// P1/P2 projection
__global__ __launch_bounds__(256)
void k_proj(const float* __restrict__ w, const float* __restrict__ bias) {
    extern __shared__ float ws[];          // 64 KB
    __shared__ float xs[32*AA];
    int tid = threadIdx.x;
    int t = tid & 63, r8 = tid >> 6;
    for (int i = tid; i < 128*TWOA; i += 256) ws[i] = w[i];
    __syncthreads();
    ull bc = f2x_pack(bias[2*t], bias[2*t+1]);
    const ull* wv = (const ull*)ws;
    const int NG = (NN + 31) / 32;
    for (int g = blockIdx.x; g < NG; g += gridDim.x) {
        int n0 = g * 32;
        int cnt = min(32, NN - n0);
        for (int i = tid; i < cnt*AA; i += 256) xs[i] = g_x[(size_t)n0*AA + i];
        __syncthreads();
        const float* xb = &xs[r8*8*AA];
        int nb = n0 + r8*8;
        ull p1[8], p2[8];
        #pragma unroll
        for (int r = 0; r < 8; r++) { p1[r] = bc; p2[r] = 0ull; }
        #pragma unroll 4
        for (int a = 0; a < AA; a++) {
            ull w1 = wv[a*64 + t];
            ull w2 = wv[(AA+a)*64 + t];
            #pragma unroll
            for (int r = 0; r < 8; r++) {
                float xf = xb[r*AA + a];
                ull xv = f2x_pack(xf, xf);
                p1[r] = f2x_fma(xv, w1, p1[r]);
                p2[r] = f2x_fma(xv, w2, p2[r]);
            }
        }
        #pragma unroll
        for (int r = 0; r < 8; r++) {
            if (nb + r < NN) {
                ((ull*)&g_P1[(size_t)(nb+r)*TWOA])[t] = p1[r];
                ((ull*)&g_P2[(size_t)(nb+r)*TWOA])[t] = p2[r];
            }
        }
        __syncthreads();
    }
}

// gated = P1[n] + P2[nbr] + nbr_fea @ W_edge ; bn1 stats (fp32 exact); store fp16.
__global__ __launch_bounds__(256, 3)
void k_edge(const float* __restrict__ we, const float* __restrict__ nbrf,
            const int* __restrict__ nidx, int layer) {
    __shared__ ulonglong2 wsv[NBRD*32];
    __shared__ float  nfs[8][6*NFS_STRIDE];
    __shared__ float  redS[TWOA], redQ[TWOA];
    int tid = threadIdx.x;
    {
        float* wf = (float*)wsv;
        for (int i = tid; i < NBRD*TWOA; i += 256) wf[i] = we[i];
    }
    __syncthreads();

    int w    = tid >> 5;
    int lane = tid & 31;
    int wg   = blockIdx.x * 8 + w;
    int nw   = gridDim.x * 8;

    ull s01 = 0ull, s23 = 0ull, q01 = 0ull, q23 = 0ull;

    const int NCH = RTOT/6;
    for (int ch = wg; ch < NCH; ch += nw) {
        int r0 = ch * 6;
        int n  = ch >> 1;
        const float* src = &nbrf[(size_t)r0 * NBRD];
        #pragma unroll
        for (int i = 0; i < 8; i++) {
            int p = lane + i*32;
            if (p < 6*NBRD) {
                int rr = p / NBRD, kk = p - rr*NBRD;
                nfs[w][rr*NFS_STRIDE + kk] = src[p];
            }
        }
        __syncwarp();
        ulonglong2 pa = ((const ulonglong2*)&g_P1[(size_t)n*TWOA])[lane];
        ull a01[6], a23[6];
        #pragma unroll
        for (int rr = 0; rr < 6; rr++) {
            int j = nidx[r0 + rr];
            ulonglong2 pb = ((const ulonglong2*)&g_P2[(size_t)j*TWOA])[lane];
            a01[rr] = f2x_add(pa.x, pb.x);
            a23[rr] = f2x_add(pa.y, pb.y);
        }
        #pragma unroll 1
        for (int kb = 0; kb < 40; kb += 4) {
            ulonglong2 w0 = wsv[(kb+0)*32 + lane];
            ulonglong2 w1 = wsv[(kb+1)*32 + lane];
            ulonglong2 w2 = wsv[(kb+2)*32 + lane];
            ulonglong2 w3 = wsv[(kb+3)*32 + lane];
            #pragma unroll
            for (int rr = 0; rr < 6; rr++) {
                float4 f = *(const float4*)&nfs[w][rr*NFS_STRIDE + kb];
                ull fx = f2x_pack(f.x, f.x);
                ull fy = f2x_pack(f.y, f.y);
                ull fz = f2x_pack(f.z, f.z);
                ull fw = f2x_pack(f.w, f.w);
                a01[rr] = f2x_fma(fx, w0.x, a01[rr]); a23[rr] = f2x_fma(fx, w0.y, a23[rr]);
                a01[rr] = f2x_fma(fy, w1.x, a01[rr]); a23[rr] = f2x_fma(fy, w1.y, a23[rr]);
                a01[rr] = f2x_fma(fz, w2.x, a01[rr]); a23[rr] = f2x_fma(fz, w2.y, a23[rr]);
                a01[rr] = f2x_fma(fw, w3.x, a01[rr]); a23[rr] = f2x_fma(fw, w3.y, a23[rr]);
            }
        }
        {
            ulonglong2 w4 = wsv[40*32 + lane];
            #pragma unroll
            for (int rr = 0; rr < 6; rr++) {
                float f = nfs[w][rr*NFS_STRIDE + 40];
                ull ff = f2x_pack(f, f);
                a01[rr] = f2x_fma(ff, w4.x, a01[rr]);
                a23[rr] = f2x_fma(ff, w4.y, a23[rr]);
            }
        }
        #pragma unroll
        for (int rr = 0; rr < 6; rr++) {
            float x0, x1, x2, x3;
            f2x_unpack(a01[rr], x0, x1);
            f2x_unpack(a23[rr], x2, x3);
            __half2 h0 = __floats2half2_rn(x0, x1);
            __half2 h1 = __floats2half2_rn(x2, x3);
            uint2 st; st.x = *(unsigned*)&h0; st.y = *(unsigned*)&h1;
            *(uint2*)&g_gatedh[(size_t)(r0+rr)*TWOA + lane*4] = st;
            s01 = f2x_add(s01, a01[rr]);
            s23 = f2x_add(s23, a23[rr]);
            q01 = f2x_fma(a01[rr], a01[rr], q01);
            q23 = f2x_fma(a23[rr], a23[rr], q23);
        }
        __syncwarp();
    }

    float s0,s1,s2,s3,q0,q1,q2,q3;
    f2x_unpack(s01, s0, s1); f2x_unpack(s23, s2, s3);
    f2x_unpack(q01, q0, q1); f2x_unpack(q23, q2, q3);

    if (tid < TWOA) { redS[tid] = 0.f; redQ[tid] = 0.f; }
    __syncthreads();
    int c = lane * 4;
    atomicAdd(&redS[c+0], s0); atomicAdd(&redQ[c+0], q0);
    atomicAdd(&redS[c+1], s1); atomicAdd(&redQ[c+1], q1);
    atomicAdd(&redS[c+2], s2); atomicAdd(&redQ[c+2], q2);
    atomicAdd(&redS[c+3], s3); atomicAdd(&redQ[c+3], q3);
    __syncthreads();
    if (tid < TWOA) {
        atomicAdd(&g_sum1[layer][tid],   (double)redS[tid]);
        atomicAdd(&g_sumsq1[layer][tid], (double)redQ[tid]);
    }
}

// bn1 (computed in prologue) -> sigmoid*softplus -> sum over M ; bn2 stats.
__global__ __launch_bounds__(256)
void k_apply(int layer, const float* __restrict__ bn1g, const float* __restrict__ bn1b) {
    __shared__ float scS[TWOA], shS[TWOA];
    int tid = threadIdx.x;
    if (tid < TWOA) {
        double mean = g_sum1[layer][tid] * (1.0 / (double)RTOT);
        double var  = g_sumsq1[layer][tid] * (1.0 / (double)RTOT) - mean * mean;
        float istd = rsqrtf((float)var + EPSB);
        float sc = istd * bn1g[tid];
        scS[tid] = sc;
        shS[tid] = bn1b[tid] - (float)mean * sc;
    }
    __syncthreads();

    int tx = tid & 15, ty = tid >> 4;
    int c0 = tx * 4;
    float4 scF = *(const float4*)&scS[c0];
    float4 shF = *(const float4*)&shS[c0];
    float4 scC = *(const float4*)&scS[AA + c0];
    float4 shC = *(const float4*)&shS[AA + c0];
    float ls0=0,ls1=0,ls2=0,ls3=0, lq0=0,lq1=0,lq2=0,lq3=0;
    for (int n = blockIdx.x*16 + ty; n < NN; n += gridDim.x*16) {
        const uint2* gp = (const uint2*)&g_gatedh[(size_t)n*(MM*TWOA)];
        float s0=0,s1=0,s2=0,s3=0;
        #pragma unroll
        for (int m = 0; m < MM; m++) {
            uint2 fraw = gp[m*32 + tx];
            uint2 craw = gp[m*32 + 16 + tx];
            float2 f01 = __half22float2(*(__half2*)&fraw.x);
            float2 f23 = __half22float2(*(__half2*)&fraw.y);
            float2 c01 = __half22float2(*(__half2*)&craw.x);
            float2 c23 = __half22float2(*(__half2*)&craw.y);
            s0 += sigmoid_fast(f01.x*scF.x + shF.x) * softplus_fast(c01.x*scC.x + shC.x);
            s1 += sigmoid_fast(f01.y*scF.y + shF.y) * softplus_fast(c01.y*scC.y + shC.y);
            s2 += sigmoid_fast(f23.x*scF.z + shF.z) * softplus_fast(c23.x*scC.z + shC.z);
            s3 += sigmoid_fast(f23.y*scF.w + shF.w) * softplus_fast(c23.y*scC.w + shC.w);
        }
        float4 outv; outv.x=s0; outv.y=s1; outv.z=s2; outv.w=s3;
        *(float4*)&g_summed[(size_t)n*AA + c0] = outv;
        ls0+=s0; lq0+=s0*s0; ls1+=s1; lq1+=s1*s1;
        ls2+=s2; lq2+=s2*s2; ls3+=s3; lq3+=s3*s3;
    }
    __shared__ float rS[AA], rQ[AA];
    if (ty == 0) {
        #pragma unroll
        for (int i = 0; i < 4; i++) { rS[c0+i] = 0.f; rQ[c0+i] = 0.f; }
    }
    __syncthreads();
    atomicAdd(&rS[c0+0], ls0); atomicAdd(&rQ[c0+0], lq0);
    atomicAdd(&rS[c0+1], ls1); atomicAdd(&rQ[c0+1], lq1);
    atomicAdd(&rS[c0+2], ls2); atomicAdd(&rQ[c0+2], lq2);
    atomicAdd(&rS[c0+3], ls3); atomicAdd(&rQ[c0+3], lq3);
    __syncthreads();
    if (ty == 0) {
        #pragma unroll
        for (int i = 0; i < 4; i++) {
            atomicAdd(&g_sum2[layer][c0+i],   (double)rS[c0+i]);
            atomicAdd(&g_sumsq2[layer][c0+i], (double)rQ[c0+i]);
        }
    }
}

// x = softplus(x + bn2(summed)) — bn2 scale computed in prologue
__global__ __launch_bounds__(256)
void k_update(int layer, const float* __restrict__ bn2g, const float* __restrict__ bn2b) {
    __shared__ float sc2[AA], sh2[AA];
    int tid = threadIdx.x;
    if (tid < AA) {
        double mean = g_sum2[layer][tid] * (1.0 / (double)NN);
        double var  = g_sumsq2[layer][tid] * (1.0 / (double)NN) - mean * mean;
        float istd = rsqrtf((float)var + EPSB);
        float sc = istd * bn2g[tid];
        sc2[tid] = sc;
        sh2[tid] = bn2b[tid] - (float)mean * sc;
    }
    __syncthreads();
    const int NV = NN*AA/4;
    for (int i4 = blockIdx.x*256 + tid; i4 < NV; i4 += gridDim.x*256) {
        int c0 = (i4 & 15) * 4;
        float4 xv = *(const float4*)&g_x[(size_t)i4*4];
        float4 sv = *(const float4*)&g_summed[(size_t)i4*4];
        float4 o;
        o.x = softplus_fast(xv.x + sv.x*sc2[c0+0] + sh2[c0+0]);
        o.y = softplus_fast(xv.y + sv.y*sc2[c0+1] + sh2[c0+1]);
        o.z = softplus_fast(xv.z + sv.z*sc2[c0+2] + sh2[c0+2]);
        o.w = softplus_fast(xv.w + sv.w*sc2[c0+3] + sh2[c0+3]);
        *(float4*)&g_x[(size_t)i4*4] = o;
    }
}

// Final stage: warp owns groups of 4 atoms. 512 threads/block.
__global__ __launch_bounds__(512)
void k_final(const int* __restrict__ cidx,
             const float* __restrict__ adjw, const float* __restrict__ adjb,
             const float* __restrict__ fc1w, const float* __restrict__ fc1b,
             const float* __restrict__ afw,  const float* __restrict__ afb,
             float* __restrict__ out2) {
    extern __shared__ float smem[];
    float* Wt   = smem;                    // Wt[o][e][d] = adjw[o][d][e]
    float* afws = Wt + 6*64*64;
    float* vst  = afws + AA*ORIG;
    float* qsh  = vst + 16*4*64;
    int tid = threadIdx.x;
    int w = tid >> 5, lane = tid & 31;
    for (int i = tid; i < 6*64*64; i += 512) {
        int o = i >> 12, rem = i & 4095, e = rem >> 6, d = rem & 63;
        Wt[i] = adjw[o*4096 + d*64 + e];
    }
    for (int i = tid; i < AA*ORIG; i += 512) afws[i] = afw[i];
    __syncthreads();

    float* vw = &vst[w*4*64];
    float* qw = &qsh[w*4*6];
    ull bias0 = *(const ull*)&afb[2*lane];
    ull bias1 = (lane < 14) ? *(const ull*)&afb[64 + 2*lane] : 0ull;

    int nwarps = gridDim.x * 16;
    int wgid   = blockIdx.x * 16 + w;
    for (int g0 = wgid*4; g0 < BB*NPCC; g0 += nwarps*4) {
        #pragma unroll
        for (int t = 0; t < 4; t++) {
            int idx = cidx[g0 + t];
            vw[t*64 + lane]      = g_x[(size_t)idx*AA + lane];
            vw[t*64 + lane + 32] = g_x[(size_t)idx*AA + lane + 32];
        }
        __syncwarp();
        float2 rv[4];
        #pragma unroll
        for (int t = 0; t < 4; t++) rv[t] = *(const float2*)&vw[t*64 + 2*lane];

        ull acc[4][6];
        #pragma unroll
        for (int t = 0; t < 4; t++)
            #pragma unroll
            for (int o = 0; o < 6; o++) acc[t][o] = 0ull;
        #pragma unroll 2
        for (int e = 0; e < 64; e++) {
            ull wv[6];
            #pragma unroll
            for (int o = 0; o < 6; o++) wv[o] = *(const ull*)&Wt[(o*64 + e)*64 + 2*lane];
            #pragma unroll
            for (int t = 0; t < 4; t++) {
                float vb = vw[t*64 + e];
                ull vbb = f2x_pack(vb, vb);
                #pragma unroll
                for (int o = 0; o < 6; o++) acc[t][o] = f2x_fma(vbb, wv[o], acc[t][o]);
            }
        }
        #pragma unroll
        for (int t = 0; t < 4; t++) {
            #pragma unroll
            for (int o = 0; o < 6; o++) {
                float lo, hi; f2x_unpack(acc[t][o], lo, hi);
                float p = lo * rv[t].x + hi * rv[t].y;
                #pragma unroll
                for (int off = 16; off; off >>= 1) p += __shfl_xor_sync(0xffffffffu, p, off);
                if (lane == 0) qw[t*6 + o] = p + adjb[o];
            }
        }
        __syncwarp();
        if (lane < 4) {
            int t = lane;
            float q[6], q2[6];
            #pragma unroll
            for (int o = 0; o < 6; o++) q[o] = qw[t*6 + o];
            #pragma unroll
            for (int j = 0; j < 6; j++) {
                float a = fc1b[j];
                #pragma unroll
                for (int o = 0; o < 6; o++) a += q[o] * fc1w[o*6 + j];
                q2[j] = a;
            }
            float mx = q2[0];
            #pragma unroll
            for (int j = 1; j < 6; j++) mx = fmaxf(mx, q2[j]);
            float se = 0.f;
            #pragma unroll
            for (int j = 0; j < 6; j++) se += __expf(q2[j] - mx);
            float lse = __logf(se);
            #pragma unroll
            for (int j = 0; j < 6; j++) g_logp[(g0 + t)*6 + j] = q2[j] - mx - lse;
        }
        {
            ull acc0[4], acc1[4];
            #pragma unroll
            for (int t = 0; t < 4; t++) { acc0[t] = bias0; acc1[t] = bias1; }
            #pragma unroll 2
            for (int a = 0; a < 64; a++) {
                ull w0 = *(const ull*)&afws[a*ORIG + 2*lane];
                ull w1 = (lane < 14) ? *(const ull*)&afws[a*ORIG + 64 + 2*lane] : 0ull;
                #pragma unroll
                for (int t = 0; t < 4; t++) {
                    float va = vw[t*64 + a];
                    ull vv = f2x_pack(va, va);
                    acc0[t] = f2x_fma(vv, w0, acc0[t]);
                    acc1[t] = f2x_fma(vv, w1, acc1[t]);
                }
            }
            #pragma unroll
            for (int t = 0; t < 4; t++) {
                *(ull*)&out2[(size_t)(g0+t)*ORIG + 2*lane] = acc0[t];
                if (lane < 14) *(ull*)&out2[(size_t)(g0+t)*ORIG + 64 + 2*lane] = acc1[t];
            }
        }
        __syncwarp();
    }
}

// edge_prob broadcast
__global__ void k_edgeprob(float* __restrict__ out) {
    __shared__ float sh[NPCC*6];
    int b = blockIdx.x;
    for (int i = threadIdx.x; i < NPCC*6; i += 256) sh[i] = g_logp[b*NPCC*6 + i];
    __syncthreads();
    float* o = out + (size_t)b * (NPCC*NPCC*6);
    for (int t = threadIdx.x; t < NPCC*NPCC*6; t += 256) o[t] = sh[t % (NPCC*6)];
}

// ---------------- host ----------------
extern "C" void kernel_launch(void* const* d_in, const int* in_sizes, int n_in,
                              void* d_out, int out_size) {
    const float* atom_fea = (const float*)d_in[0];
    const float* nbr_fea  = (const float*)d_in[1];
    const int*   nbr_idx  = (const int*)  d_in[2];
    const int*   cidx     = (const int*)  d_in[3];
    const float* emb_w    = (const float*)d_in[4];
    const float* fcw      = (const float*)d_in[5];
    const float* fcb      = (const float*)d_in[6];
    const float* bn1g     = (const float*)d_in[7];
    const float* bn1b     = (const float*)d_in[8];
    const float* bn2g     = (const float*)d_in[9];
    const float* bn2b     = (const float*)d_in[10];
    const float* adjw     = (const float*)d_in[11];
    const float* adjb     = (const float*)d_in[12];
    const float* fc1w     = (const float*)d_in[13];
    const float* fc1b     = (const float*)d_in[14];
    const float* afw      = (const float*)d_in[15];
    const float* afb      = (const float*)d_in[16];
    float* out = (float*)d_out;

    const int PROJ_SMEM  = 128 * TWOA * sizeof(float);
    const int FINAL_SMEM = (6*64*64 + AA*ORIG + 16*4*64 + 16*4*6) * sizeof(float);
    cudaFuncSetAttribute(k_proj,  cudaFuncAttributeMaxDynamicSharedMemorySize, PROJ_SMEM);
    cudaFuncSetAttribute(k_final, cudaFuncAttributeMaxDynamicSharedMemorySize, FINAL_SMEM);

    k_zero_stats<<<1, 256>>>();
    k_embed<<<1184, 256>>>(atom_fea, emb_w);

    for (int i = 0; i < 3; i++) {
        const float* w = fcw + i * (2*AA + NBRD) * TWOA;
        k_proj<<<444, 256, PROJ_SMEM>>>(w, fcb + i*TWOA);
        k_edge<<<444, 256>>>(w + 2*AA*TWOA, nbr_fea, nbr_idx, i);
        k_apply<<<1184, 256>>>(i, bn1g + i*TWOA, bn1b + i*TWOA);
        k_update<<<592, 256>>>(i, bn2g + i*AA, bn2b + i*AA);
    }

    float* out_atomfea = out + (size_t)BB * NPCC * NPCC * 6;
    k_final<<<148, 512, FINAL_SMEM>>>(cidx, adjw, adjb, fc1w, fc1b, afw, afb, out_atomfea);
    k_edgeprob<<<BB, 256>>>(out);
}